// round 2
// baseline (speedup 1.0000x reference)
#include <cuda_runtime.h>
#include <math.h>

// Problem constants
#define TQ    2048
#define CD    1024
#define NHEAD 16
#define HDIM  64
#define BATCH 2
#define MROWS (BATCH*TQ)        // 4096
#define YSZ   (BATCH*TQ*CD)     // 4194304 floats per output section

// Scratch (device globals; no allocation allowed)
__device__ float g_Q[BATCH*NHEAD*TQ*HDIM];   // Q in [B,H,T,hd]
__device__ float g_Yatt[BATCH*TQ*CD];        // attention out in [B,T,C]

// ---------------------------------------------------------------------------
// Classic 128x128x8 register-blocked SGEMM, 256 threads, 8x8 per thread.
// qkv variant: C = x @ W_attn + b_attn, scatter to (g_Q | Kout | Vout)
// ---------------------------------------------------------------------------
__global__ __launch_bounds__(256) void qkv_gemm(
    const float* __restrict__ A,      // [4096,1024]
    const float* __restrict__ W,      // [1024,3072]
    const float* __restrict__ bias,   // [3072]
    float* __restrict__ Kout,         // [B,H,T,hd]
    float* __restrict__ Vout)         // [B,H,T,hd]
{
    const int N = 3*CD, K = CD;
    __shared__ float As[8*128];   // transposed: As[k][m]
    __shared__ float Bs[8*128];   // Bs[k][n]
    const int t = threadIdx.x;
    const int m0 = blockIdx.y * 128, n0 = blockIdx.x * 128;
    const int ty = t >> 4, tx = t & 15;

    float acc[8][8];
#pragma unroll
    for (int i = 0; i < 8; i++)
#pragma unroll
        for (int j = 0; j < 8; j++) acc[i][j] = 0.f;

    const int arow = t >> 1, akq = (t & 1) * 4;
    const int brow = t >> 5, bnq = (t & 31) * 4;
    const float* Aptr = A + (size_t)(m0 + arow) * K + akq;
    const float* Bptr = W + (size_t)brow * N + n0 + bnq;

    for (int kt = 0; kt < K; kt += 8) {
        float4 a4 = *(const float4*)(Aptr + kt);
        float4 b4 = *(const float4*)(Bptr + (size_t)kt * N);
        As[(akq+0)*128 + arow] = a4.x;
        As[(akq+1)*128 + arow] = a4.y;
        As[(akq+2)*128 + arow] = a4.z;
        As[(akq+3)*128 + arow] = a4.w;
        *(float4*)(Bs + brow*128 + bnq) = b4;
        __syncthreads();
#pragma unroll
        for (int kk = 0; kk < 8; kk++) {
            float a[8], b[8];
            *(float4*)(a)   = *(const float4*)(As + kk*128 + ty*8);
            *(float4*)(a+4) = *(const float4*)(As + kk*128 + ty*8 + 4);
            *(float4*)(b)   = *(const float4*)(Bs + kk*128 + tx*8);
            *(float4*)(b+4) = *(const float4*)(Bs + kk*128 + tx*8 + 4);
#pragma unroll
            for (int i = 0; i < 8; i++)
#pragma unroll
                for (int j = 0; j < 8; j++)
                    acc[i][j] = fmaf(a[i], b[j], acc[i][j]);
        }
        __syncthreads();
    }

    // Epilogue: bias + scatter. Each float4 group stays inside one head/section.
#pragma unroll
    for (int i = 0; i < 8; i++) {
        int m  = m0 + ty*8 + i;
        int b  = m >> 11;           // /2048
        int tt = m & (TQ - 1);
#pragma unroll
        for (int j4 = 0; j4 < 8; j4 += 4) {
            int n = n0 + tx*8 + j4;
            float4 v;
            v.x = acc[i][j4+0] + bias[n+0];
            v.y = acc[i][j4+1] + bias[n+1];
            v.z = acc[i][j4+2] + bias[n+2];
            v.w = acc[i][j4+3] + bias[n+3];
            int sec    = n >> 10;
            int within = n & 1023;
            int h = within >> 6, d = within & 63;
            size_t idx = ((size_t)(b*NHEAD + h)*TQ + tt)*HDIM + d;
            float* dst = (sec == 0) ? g_Q : (sec == 1 ? Kout : Vout);
            *(float4*)(dst + idx) = v;
        }
    }
}

// ---------------------------------------------------------------------------
// Proj variant: out = g_Yatt @ W_proj + b_proj  -> d_out y region
// ---------------------------------------------------------------------------
__global__ __launch_bounds__(256) void proj_gemm(
    const float* __restrict__ W,      // [1024,1024]
    const float* __restrict__ bias,   // [1024]
    float* __restrict__ out)          // [4096,1024]
{
    const int N = CD, K = CD;
    __shared__ float As[8*128];
    __shared__ float Bs[8*128];
    const int t = threadIdx.x;
    const int m0 = blockIdx.y * 128, n0 = blockIdx.x * 128;
    const int ty = t >> 4, tx = t & 15;

    float acc[8][8];
#pragma unroll
    for (int i = 0; i < 8; i++)
#pragma unroll
        for (int j = 0; j < 8; j++) acc[i][j] = 0.f;

    const int arow = t >> 1, akq = (t & 1) * 4;
    const int brow = t >> 5, bnq = (t & 31) * 4;
    const float* Aptr = g_Yatt + (size_t)(m0 + arow) * K + akq;
    const float* Bptr = W + (size_t)brow * N + n0 + bnq;

    for (int kt = 0; kt < K; kt += 8) {
        float4 a4 = *(const float4*)(Aptr + kt);
        float4 b4 = *(const float4*)(Bptr + (size_t)kt * N);
        As[(akq+0)*128 + arow] = a4.x;
        As[(akq+1)*128 + arow] = a4.y;
        As[(akq+2)*128 + arow] = a4.z;
        As[(akq+3)*128 + arow] = a4.w;
        *(float4*)(Bs + brow*128 + bnq) = b4;
        __syncthreads();
#pragma unroll
        for (int kk = 0; kk < 8; kk++) {
            float a[8], b[8];
            *(float4*)(a)   = *(const float4*)(As + kk*128 + ty*8);
            *(float4*)(a+4) = *(const float4*)(As + kk*128 + ty*8 + 4);
            *(float4*)(b)   = *(const float4*)(Bs + kk*128 + tx*8);
            *(float4*)(b+4) = *(const float4*)(Bs + kk*128 + tx*8 + 4);
#pragma unroll
            for (int i = 0; i < 8; i++)
#pragma unroll
                for (int j = 0; j < 8; j++)
                    acc[i][j] = fmaf(a[i], b[j], acc[i][j]);
        }
        __syncthreads();
    }

#pragma unroll
    for (int i = 0; i < 8; i++) {
        int m = m0 + ty*8 + i;
#pragma unroll
        for (int j4 = 0; j4 < 8; j4 += 4) {
            int n = n0 + tx*8 + j4;
            float4 v;
            v.x = acc[i][j4+0] + bias[n+0];
            v.y = acc[i][j4+1] + bias[n+1];
            v.z = acc[i][j4+2] + bias[n+2];
            v.w = acc[i][j4+3] + bias[n+3];
            *(float4*)(out + (size_t)m*N + n) = v;
        }
    }
}

// ---------------------------------------------------------------------------
// Flash-style causal attention. One CTA = one (bh, 64-query tile).
// 256 threads. SMEM tiles 64x64 (padded to 68 for alignment+banks).
// ---------------------------------------------------------------------------
#define LD 68
#define ATTN_SMEM (4*64*LD*sizeof(float))   // 69632 B

__global__ __launch_bounds__(256) void attn_kernel(
    const float* __restrict__ Kg,   // [B,H,T,hd]
    const float* __restrict__ Vg)   // [B,H,T,hd]
{
    extern __shared__ float sm[];
    float* Qs = sm;
    float* Ks = sm + 64*LD;
    float* Vs = sm + 2*64*LD;
    float* Ss = sm + 3*64*LD;

    const int bh = blockIdx.y;
    const int qb = gridDim.x - 1 - blockIdx.x;  // big tiles first (load balance)
    const int t  = threadIdx.x;
    const int q0 = qb * 64;

    const int lr  = t >> 2;           // row 0..63 (load/softmax/O mapping)
    const int lc0 = (t & 3) * 16;     // 16-wide column slice
    const int cq  = t & 3;
    const int tr  = t >> 4, tc = t & 15;  // S-gemm 4x4 microtile mapping

    // Load Q tile
    const float* Qb = g_Q + ((size_t)bh*TQ + q0) * HDIM;
#pragma unroll
    for (int i = 0; i < 16; i += 4)
        *(float4*)(Qs + lr*LD + lc0 + i) = *(const float4*)(Qb + lr*HDIM + lc0 + i);

    float mrun = -1e30f, lrun = 0.f;
    float O[16];
#pragma unroll
    for (int i = 0; i < 16; i++) O[i] = 0.f;
    __syncthreads();

    for (int kb = 0; kb <= qb; kb++) {
        const int k0 = kb * 64;
        const float* Kb = Kg + ((size_t)bh*TQ + k0) * HDIM;
        const float* Vb = Vg + ((size_t)bh*TQ + k0) * HDIM;
#pragma unroll
        for (int i = 0; i < 16; i += 4) {
            *(float4*)(Ks + lr*LD + lc0 + i) = *(const float4*)(Kb + lr*HDIM + lc0 + i);
            *(float4*)(Vs + lr*LD + lc0 + i) = *(const float4*)(Vb + lr*HDIM + lc0 + i);
        }
        __syncthreads();

        // S = Q K^T  (64x64, 4x4 per thread)
        float S[4][4];
#pragma unroll
        for (int i = 0; i < 4; i++)
#pragma unroll
            for (int j = 0; j < 4; j++) S[i][j] = 0.f;

        for (int d0 = 0; d0 < HDIM; d0 += 4) {
            float4 a[4], b[4];
#pragma unroll
            for (int i = 0; i < 4; i++) a[i] = *(const float4*)(Qs + (tr*4+i)*LD + d0);
#pragma unroll
            for (int j = 0; j < 4; j++) b[j] = *(const float4*)(Ks + (tc*4+j)*LD + d0);
#pragma unroll
            for (int i = 0; i < 4; i++)
#pragma unroll
                for (int j = 0; j < 4; j++) {
                    S[i][j] = fmaf(a[i].x, b[j].x, S[i][j]);
                    S[i][j] = fmaf(a[i].y, b[j].y, S[i][j]);
                    S[i][j] = fmaf(a[i].z, b[j].z, S[i][j]);
                    S[i][j] = fmaf(a[i].w, b[j].w, S[i][j]);
                }
        }

        // scale + causal mask (only diagonal block needs per-element mask)
        const bool diag = (kb == qb);
#pragma unroll
        for (int i = 0; i < 4; i++)
#pragma unroll
            for (int j = 0; j < 4; j++) {
                float v = S[i][j] * 0.125f;   // 1/sqrt(64)
                if (diag && (tc*4 + j) > (tr*4 + i)) v = -1e30f;
                Ss[(tr*4+i)*LD + tc*4 + j] = v;
            }
        __syncthreads();

        // Online softmax: thread (lr, cq) owns 16 entries of row lr
        float p[16];
        float mx = -1e30f;
#pragma unroll
        for (int jj = 0; jj < 16; jj++) {
            p[jj] = Ss[lr*LD + cq*16 + jj];
            mx = fmaxf(mx, p[jj]);
        }
        mx = fmaxf(mx, __shfl_xor_sync(0xffffffffu, mx, 1));
        mx = fmaxf(mx, __shfl_xor_sync(0xffffffffu, mx, 2));
        float mnew  = fmaxf(mrun, mx);
        float alpha = __expf(mrun - mnew);
        float psum  = 0.f;
#pragma unroll
        for (int jj = 0; jj < 16; jj++) {
            float e = __expf(p[jj] - mnew);
            psum += e;
            Ss[lr*LD + cq*16 + jj] = e;
        }
        psum += __shfl_xor_sync(0xffffffffu, psum, 1);
        psum += __shfl_xor_sync(0xffffffffu, psum, 2);
        lrun = lrun * alpha + psum;
        mrun = mnew;
#pragma unroll
        for (int jj = 0; jj < 16; jj++) O[jj] *= alpha;
        __syncthreads();

        // O += P @ V  (thread owns row lr, dims lc0..lc0+15)
#pragma unroll 4
        for (int j = 0; j < 64; j++) {
            float pw = Ss[lr*LD + j];
            float4 v0 = *(const float4*)(Vs + j*LD + lc0 + 0);
            float4 v1 = *(const float4*)(Vs + j*LD + lc0 + 4);
            float4 v2 = *(const float4*)(Vs + j*LD + lc0 + 8);
            float4 v3 = *(const float4*)(Vs + j*LD + lc0 + 12);
            O[0]  = fmaf(pw, v0.x, O[0]);  O[1]  = fmaf(pw, v0.y, O[1]);
            O[2]  = fmaf(pw, v0.z, O[2]);  O[3]  = fmaf(pw, v0.w, O[3]);
            O[4]  = fmaf(pw, v1.x, O[4]);  O[5]  = fmaf(pw, v1.y, O[5]);
            O[6]  = fmaf(pw, v1.z, O[6]);  O[7]  = fmaf(pw, v1.w, O[7]);
            O[8]  = fmaf(pw, v2.x, O[8]);  O[9]  = fmaf(pw, v2.y, O[9]);
            O[10] = fmaf(pw, v2.z, O[10]); O[11] = fmaf(pw, v2.w, O[11]);
            O[12] = fmaf(pw, v3.x, O[12]); O[13] = fmaf(pw, v3.y, O[13]);
            O[14] = fmaf(pw, v3.z, O[14]); O[15] = fmaf(pw, v3.w, O[15]);
        }
        __syncthreads();
    }

    // Write normalized output in [B,T,C] layout (proj-ready)
    const float inv = 1.f / lrun;
    const int b = bh >> 4, h = bh & 15;
    float* yp = g_Yatt + ((size_t)(b*TQ + q0 + lr)) * CD + h*HDIM + lc0;
#pragma unroll
    for (int i = 0; i < 16; i += 4) {
        float4 v;
        v.x = O[i+0] * inv; v.y = O[i+1] * inv;
        v.z = O[i+2] * inv; v.w = O[i+3] * inv;
        *(float4*)(yp + i) = v;
    }
}

// ---------------------------------------------------------------------------
extern "C" void kernel_launch(void* const* d_in, const int* in_sizes, int n_in,
                              void* d_out, int out_size)
{
    const float* x      = (const float*)d_in[0];
    const float* W_attn = (const float*)d_in[1];
    const float* b_attn = (const float*)d_in[2];
    const float* W_proj = (const float*)d_in[3];
    const float* b_proj = (const float*)d_in[4];
    float* out  = (float*)d_out;
    float* Kout = out + (size_t)YSZ;        // present_k [B,H,T,hd]
    float* Vout = out + 2*(size_t)YSZ;      // present_v [B,H,T,hd]

    // 1) qkv projection: q -> g_Q, k/v -> d_out (they ARE the k/v outputs)
    qkv_gemm<<<dim3(3*CD/128, MROWS/128), 256>>>(x, W_attn, b_attn, Kout, Vout);

    // 2) causal flash attention -> g_Yatt [B,T,C]
    cudaFuncSetAttribute(attn_kernel, cudaFuncAttributeMaxDynamicSharedMemorySize,
                         (int)ATTN_SMEM);
    attn_kernel<<<dim3(TQ/64, BATCH*NHEAD), 256, ATTN_SMEM>>>(Kout, Vout);

    // 3) output projection -> d_out y region
    proj_gemm<<<dim3(CD/128, MROWS/128), 256>>>(W_proj, b_proj, out);
}

// round 3
// speedup vs baseline: 1.8929x; 1.8929x over previous
#include <cuda_runtime.h>

// Problem constants
#define TQ    2048
#define CD    1024
#define NHEAD 16
#define HDIM  64
#define BATCH 2
#define MROWS (BATCH*TQ)        // 4096
#define YSZ   (BATCH*TQ*CD)     // floats per output section

typedef unsigned long long u64;

// ---- packed f32x2 helpers (Blackwell FFMA2 path; 2x FFMA-3reg throughput) ----
__device__ __forceinline__ u64 splat2(float x) {
    u64 r; asm("mov.b64 %0, {%1, %1};" : "=l"(r) : "f"(x)); return r;
}
__device__ __forceinline__ void unpack2(u64 v, float &x, float &y) {
    asm("mov.b64 {%0, %1}, %2;" : "=f"(x), "=f"(y) : "l"(v));
}
__device__ __forceinline__ void ffma2(u64 &d, u64 a, u64 b) {
    asm("fma.rn.f32x2 %0, %1, %2, %0;" : "+l"(d) : "l"(a), "l"(b));
}
__device__ __forceinline__ void fmul2(u64 &d, u64 a, u64 b) {
    asm("mul.rn.f32x2 %0, %1, %2;" : "=l"(d) : "l"(a), "l"(b));
}

// Scratch (device globals; no allocation allowed)
__device__ float g_Q[BATCH*NHEAD*TQ*HDIM];   // Q in [B,H,T,hd]
__device__ float g_Yatt[BATCH*TQ*CD];        // attention out in [B,T,C]

// ---------------------------------------------------------------------------
// 128x128x8 register-blocked SGEMM, double-buffered, f32x2 accumulators.
// qkv variant: C = x @ W_attn + b_attn, scatter to (g_Q | Kout | Vout)
// ---------------------------------------------------------------------------
__global__ __launch_bounds__(256) void qkv_gemm(
    const float* __restrict__ A,      // [4096,1024]
    const float* __restrict__ W,      // [1024,3072]
    const float* __restrict__ bias,   // [3072]
    float* __restrict__ Kout,
    float* __restrict__ Vout)
{
    const int N = 3*CD, K = CD;
    __shared__ float As[2][8*128];
    __shared__ float Bs[2][8*128];
    const int t = threadIdx.x;
    const int m0 = blockIdx.y * 128, n0 = blockIdx.x * 128;
    const int ty = t >> 4, tx = t & 15;

    u64 acc[8][4];
#pragma unroll
    for (int i = 0; i < 8; i++)
#pragma unroll
        for (int j = 0; j < 4; j++) acc[i][j] = 0ULL;

    const int arow = t >> 1, akq = (t & 1) * 4;
    const int brow = t >> 5, bnq = (t & 31) * 4;
    const float* Aptr = A + (size_t)(m0 + arow) * K + akq;
    const float* Bptr = W + (size_t)brow * N + n0 + bnq;

    // preload tile 0
    {
        float4 a4 = *(const float4*)(Aptr);
        float4 b4 = *(const float4*)(Bptr);
        As[0][(akq+0)*128 + arow] = a4.x;
        As[0][(akq+1)*128 + arow] = a4.y;
        As[0][(akq+2)*128 + arow] = a4.z;
        As[0][(akq+3)*128 + arow] = a4.w;
        *(float4*)(&Bs[0][brow*128 + bnq]) = b4;
    }
    __syncthreads();

    int cur = 0;
    for (int kt = 0; kt < K; kt += 8) {
        float4 an, bn;
        const bool more = (kt + 8 < K);
        if (more) {
            an = *(const float4*)(Aptr + kt + 8);
            bn = *(const float4*)(Bptr + (size_t)(kt + 8) * N);
        }
#pragma unroll
        for (int kk = 0; kk < 8; kk++) {
            float a[8];
            *(float4*)(a)   = *(const float4*)(&As[cur][kk*128 + ty*8]);
            *(float4*)(a+4) = *(const float4*)(&As[cur][kk*128 + ty*8 + 4]);
            const u64* bp = (const u64*)(&Bs[cur][kk*128 + tx*8]);
            u64 b0 = bp[0], b1 = bp[1], b2 = bp[2], b3 = bp[3];
#pragma unroll
            for (int i = 0; i < 8; i++) {
                u64 sa = splat2(a[i]);
                ffma2(acc[i][0], sa, b0);
                ffma2(acc[i][1], sa, b1);
                ffma2(acc[i][2], sa, b2);
                ffma2(acc[i][3], sa, b3);
            }
        }
        if (more) {
            int nx = cur ^ 1;
            As[nx][(akq+0)*128 + arow] = an.x;
            As[nx][(akq+1)*128 + arow] = an.y;
            As[nx][(akq+2)*128 + arow] = an.z;
            As[nx][(akq+3)*128 + arow] = an.w;
            *(float4*)(&Bs[nx][brow*128 + bnq]) = bn;
        }
        __syncthreads();
        cur ^= 1;
    }

    // Epilogue: unpack, bias, scatter
    float c[8][8];
#pragma unroll
    for (int i = 0; i < 8; i++)
#pragma unroll
        for (int jp = 0; jp < 4; jp++)
            unpack2(acc[i][jp], c[i][2*jp], c[i][2*jp+1]);

#pragma unroll
    for (int i = 0; i < 8; i++) {
        int m  = m0 + ty*8 + i;
        int b  = m >> 11;
        int tt = m & (TQ - 1);
#pragma unroll
        for (int j4 = 0; j4 < 8; j4 += 4) {
            int n = n0 + tx*8 + j4;
            float4 v;
            v.x = c[i][j4+0] + bias[n+0];
            v.y = c[i][j4+1] + bias[n+1];
            v.z = c[i][j4+2] + bias[n+2];
            v.w = c[i][j4+3] + bias[n+3];
            int sec    = n >> 10;
            int within = n & 1023;
            int h = within >> 6, d = within & 63;
            size_t idx = ((size_t)(b*NHEAD + h)*TQ + tt)*HDIM + d;
            float* dst = (sec == 0) ? g_Q : (sec == 1 ? Kout : Vout);
            *(float4*)(dst + idx) = v;
        }
    }
}

// ---------------------------------------------------------------------------
// Proj: out = g_Yatt @ W_proj + b_proj (same structure)
// ---------------------------------------------------------------------------
__global__ __launch_bounds__(256) void proj_gemm(
    const float* __restrict__ W,
    const float* __restrict__ bias,
    float* __restrict__ out)
{
    const int N = CD, K = CD;
    __shared__ float As[2][8*128];
    __shared__ float Bs[2][8*128];
    const int t = threadIdx.x;
    const int m0 = blockIdx.y * 128, n0 = blockIdx.x * 128;
    const int ty = t >> 4, tx = t & 15;

    u64 acc[8][4];
#pragma unroll
    for (int i = 0; i < 8; i++)
#pragma unroll
        for (int j = 0; j < 4; j++) acc[i][j] = 0ULL;

    const int arow = t >> 1, akq = (t & 1) * 4;
    const int brow = t >> 5, bnq = (t & 31) * 4;
    const float* Aptr = g_Yatt + (size_t)(m0 + arow) * K + akq;
    const float* Bptr = W + (size_t)brow * N + n0 + bnq;

    {
        float4 a4 = *(const float4*)(Aptr);
        float4 b4 = *(const float4*)(Bptr);
        As[0][(akq+0)*128 + arow] = a4.x;
        As[0][(akq+1)*128 + arow] = a4.y;
        As[0][(akq+2)*128 + arow] = a4.z;
        As[0][(akq+3)*128 + arow] = a4.w;
        *(float4*)(&Bs[0][brow*128 + bnq]) = b4;
    }
    __syncthreads();

    int cur = 0;
    for (int kt = 0; kt < K; kt += 8) {
        float4 an, bn;
        const bool more = (kt + 8 < K);
        if (more) {
            an = *(const float4*)(Aptr + kt + 8);
            bn = *(const float4*)(Bptr + (size_t)(kt + 8) * N);
        }
#pragma unroll
        for (int kk = 0; kk < 8; kk++) {
            float a[8];
            *(float4*)(a)   = *(const float4*)(&As[cur][kk*128 + ty*8]);
            *(float4*)(a+4) = *(const float4*)(&As[cur][kk*128 + ty*8 + 4]);
            const u64* bp = (const u64*)(&Bs[cur][kk*128 + tx*8]);
            u64 b0 = bp[0], b1 = bp[1], b2 = bp[2], b3 = bp[3];
#pragma unroll
            for (int i = 0; i < 8; i++) {
                u64 sa = splat2(a[i]);
                ffma2(acc[i][0], sa, b0);
                ffma2(acc[i][1], sa, b1);
                ffma2(acc[i][2], sa, b2);
                ffma2(acc[i][3], sa, b3);
            }
        }
        if (more) {
            int nx = cur ^ 1;
            As[nx][(akq+0)*128 + arow] = an.x;
            As[nx][(akq+1)*128 + arow] = an.y;
            As[nx][(akq+2)*128 + arow] = an.z;
            As[nx][(akq+3)*128 + arow] = an.w;
            *(float4*)(&Bs[nx][brow*128 + bnq]) = bn;
        }
        __syncthreads();
        cur ^= 1;
    }

    float c[8][8];
#pragma unroll
    for (int i = 0; i < 8; i++)
#pragma unroll
        for (int jp = 0; jp < 4; jp++)
            unpack2(acc[i][jp], c[i][2*jp], c[i][2*jp+1]);

#pragma unroll
    for (int i = 0; i < 8; i++) {
        int m = m0 + ty*8 + i;
#pragma unroll
        for (int j4 = 0; j4 < 8; j4 += 4) {
            int n = n0 + tx*8 + j4;
            float4 v;
            v.x = c[i][j4+0] + bias[n+0];
            v.y = c[i][j4+1] + bias[n+1];
            v.z = c[i][j4+2] + bias[n+2];
            v.w = c[i][j4+3] + bias[n+3];
            *(float4*)(out + (size_t)m*N + n) = v;
        }
    }
}

// ---------------------------------------------------------------------------
// Flash attention v2: BM=128 queries x BN=128 keys per iteration, 256 threads.
// S in registers (8x8 per thread, f32x2-paired), softmax in regs via shfl,
// one P round-trip through SMEM, f32x2 PV gemm.
// ---------------------------------------------------------------------------
#define BM 128
#define BN 128
#define LDT 132   // Qt/Kt: [64][BM/BN + 4]
#define LDV 68    // Vs: [BN][HDIM + 4]
#define LDP 132   // Ps: [BM][BN + 4]
#define ATTN_SMEM ((64*LDT*2 + BN*LDV + BM*LDP + 2*BM) * sizeof(float))

__global__ __launch_bounds__(256) void attn2(
    const float* __restrict__ Kg,   // [B,H,T,hd]
    const float* __restrict__ Vg)
{
    extern __shared__ float sm[];
    float* Qt = sm;                 // [64][LDT] d-major, pre-scaled by 1/8
    float* Kt = Qt + 64*LDT;        // [64][LDT] d-major
    float* Vs = Kt + 64*LDT;        // [BN][LDV] row-major
    float* Ps = Vs + BN*LDV;        // [BM][LDP]
    float* aB = Ps + (size_t)BM*LDP;  // [BM] per-row alpha
    float* lB = aB + BM;              // [BM] per-row 1/l

    const int bh = blockIdx.y;
    const int qb = gridDim.x - 1 - blockIdx.x;  // big tiles first
    const int q0 = qb * BM;
    const int t  = threadIdx.x;
    const int ty = t >> 4, tx = t & 15;          // softmax/S mapping (16x16)
    const int g  = t >> 3, ec = (t & 7) * 8;     // PV mapping (32 row-grps x 8 e-grps)

    // Load Q tile transposed (d-major), pre-scaled by 1/sqrt(hd)
    const float* Qb = g_Q + ((size_t)bh*TQ + q0) * HDIM;
    for (int i = t; i < BM*16; i += 256) {
        int m = i >> 4, dq = (i & 15) << 2;
        float4 v = *(const float4*)(Qb + m*HDIM + dq);
        Qt[(dq+0)*LDT + m] = v.x * 0.125f;
        Qt[(dq+1)*LDT + m] = v.y * 0.125f;
        Qt[(dq+2)*LDT + m] = v.z * 0.125f;
        Qt[(dq+3)*LDT + m] = v.w * 0.125f;
    }

    float row_m[8], row_l[8];
#pragma unroll
    for (int i = 0; i < 8; i++) { row_m[i] = -1e30f; row_l[i] = 0.f; }
    u64 O2[4][4];
#pragma unroll
    for (int i = 0; i < 4; i++)
#pragma unroll
        for (int c = 0; c < 4; c++) O2[i][c] = 0ULL;

    for (int kb = 0; kb <= qb; kb++) {
        const int k0 = kb * BN;
        const float* Kb = Kg + ((size_t)bh*TQ + k0) * HDIM;
        const float* Vb = Vg + ((size_t)bh*TQ + k0) * HDIM;
        for (int i = t; i < BN*16; i += 256) {
            int n = i >> 4, dq = (i & 15) << 2;
            float4 kv = *(const float4*)(Kb + n*HDIM + dq);
            Kt[(dq+0)*LDT + n] = kv.x;
            Kt[(dq+1)*LDT + n] = kv.y;
            Kt[(dq+2)*LDT + n] = kv.z;
            Kt[(dq+3)*LDT + n] = kv.w;
            *(float4*)(Vs + n*LDV + dq) = *(const float4*)(Vb + n*HDIM + dq);
        }
        __syncthreads();

        // S = Q K^T : thread (ty,tx) -> rows ty*8.., cols tx*8.. (f32x2-paired)
        u64 S2[8][4];
#pragma unroll
        for (int i = 0; i < 8; i++)
#pragma unroll
            for (int jp = 0; jp < 4; jp++) S2[i][jp] = 0ULL;

#pragma unroll 4
        for (int d = 0; d < HDIM; d++) {
            float a[8];
            *(float4*)(a)   = *(const float4*)(Qt + d*LDT + ty*8);
            *(float4*)(a+4) = *(const float4*)(Qt + d*LDT + ty*8 + 4);
            const u64* bp = (const u64*)(Kt + d*LDT + tx*8);
            u64 b0 = bp[0], b1 = bp[1], b2 = bp[2], b3 = bp[3];
#pragma unroll
            for (int i = 0; i < 8; i++) {
                u64 sa = splat2(a[i]);
                ffma2(S2[i][0], sa, b0);
                ffma2(S2[i][1], sa, b1);
                ffma2(S2[i][2], sa, b2);
                ffma2(S2[i][3], sa, b3);
            }
        }

        // Online softmax (rows live in 16-lane groups of same ty)
        const bool diag = (kb == qb);
#pragma unroll
        for (int i = 0; i < 8; i++) {
            float v[8];
            unpack2(S2[i][0], v[0], v[1]);
            unpack2(S2[i][1], v[2], v[3]);
            unpack2(S2[i][2], v[4], v[5]);
            unpack2(S2[i][3], v[6], v[7]);
            const int r = ty*8 + i;
            if (diag) {
#pragma unroll
                for (int j = 0; j < 8; j++)
                    if (tx*8 + j > r) v[j] = -1e30f;
            }
            float mx = v[0];
#pragma unroll
            for (int j = 1; j < 8; j++) mx = fmaxf(mx, v[j]);
            mx = fmaxf(mx, __shfl_xor_sync(0xffffffffu, mx, 1));
            mx = fmaxf(mx, __shfl_xor_sync(0xffffffffu, mx, 2));
            mx = fmaxf(mx, __shfl_xor_sync(0xffffffffu, mx, 4));
            mx = fmaxf(mx, __shfl_xor_sync(0xffffffffu, mx, 8));
            float mnew = fmaxf(row_m[i], mx);
            float al   = __expf(row_m[i] - mnew);
            float s = 0.f;
#pragma unroll
            for (int j = 0; j < 8; j++) {
                v[j] = __expf(v[j] - mnew);
                s += v[j];
            }
            s += __shfl_xor_sync(0xffffffffu, s, 1);
            s += __shfl_xor_sync(0xffffffffu, s, 2);
            s += __shfl_xor_sync(0xffffffffu, s, 4);
            s += __shfl_xor_sync(0xffffffffu, s, 8);
            row_l[i] = row_l[i] * al + s;
            row_m[i] = mnew;
            if (tx == 0) aB[r] = al;
            *(float4*)(Ps + (size_t)r*LDP + tx*8)     = make_float4(v[0], v[1], v[2], v[3]);
            *(float4*)(Ps + (size_t)r*LDP + tx*8 + 4) = make_float4(v[4], v[5], v[6], v[7]);
        }
        __syncthreads();

        // O *= alpha; O += P @ V (thread: rows g*4.., cols ec..ec+7 paired)
#pragma unroll
        for (int i = 0; i < 4; i++) {
            u64 al2 = splat2(aB[g*4 + i]);
            fmul2(O2[i][0], O2[i][0], al2);
            fmul2(O2[i][1], O2[i][1], al2);
            fmul2(O2[i][2], O2[i][2], al2);
            fmul2(O2[i][3], O2[i][3], al2);
        }
#pragma unroll 2
        for (int j = 0; j < BN; j += 2) {
            const u64* vpa = (const u64*)(Vs + j*LDV + ec);
            const u64* vpb = (const u64*)(Vs + (j+1)*LDV + ec);
            u64 va0 = vpa[0], va1 = vpa[1], va2 = vpa[2], va3 = vpa[3];
            u64 vb0 = vpb[0], vb1 = vpb[1], vb2 = vpb[2], vb3 = vpb[3];
#pragma unroll
            for (int i = 0; i < 4; i++) {
                u64 p2 = *(const u64*)(Ps + (size_t)(g*4+i)*LDP + j);
                float plo, phi;
                unpack2(p2, plo, phi);
                u64 sl = splat2(plo), sh = splat2(phi);
                ffma2(O2[i][0], sl, va0);
                ffma2(O2[i][1], sl, va1);
                ffma2(O2[i][2], sl, va2);
                ffma2(O2[i][3], sl, va3);
                ffma2(O2[i][0], sh, vb0);
                ffma2(O2[i][1], sh, vb1);
                ffma2(O2[i][2], sh, vb2);
                ffma2(O2[i][3], sh, vb3);
            }
        }
        __syncthreads();
    }

    // finalize
    if (tx == 0) {
#pragma unroll
        for (int i = 0; i < 8; i++) lB[ty*8 + i] = 1.f / row_l[i];
    }
    __syncthreads();

    const int b = bh >> 4, h = bh & 15;
#pragma unroll
    for (int i = 0; i < 4; i++) {
        float inv = lB[g*4 + i];
        float o[8];
        unpack2(O2[i][0], o[0], o[1]);
        unpack2(O2[i][1], o[2], o[3]);
        unpack2(O2[i][2], o[4], o[5]);
        unpack2(O2[i][3], o[6], o[7]);
        float* yp = g_Yatt + ((size_t)(b*TQ + q0 + g*4 + i))*CD + h*HDIM + ec;
        *(float4*)(yp)     = make_float4(o[0]*inv, o[1]*inv, o[2]*inv, o[3]*inv);
        *(float4*)(yp + 4) = make_float4(o[4]*inv, o[5]*inv, o[6]*inv, o[7]*inv);
    }
}

// ---------------------------------------------------------------------------
extern "C" void kernel_launch(void* const* d_in, const int* in_sizes, int n_in,
                              void* d_out, int out_size)
{
    const float* x      = (const float*)d_in[0];
    const float* W_attn = (const float*)d_in[1];
    const float* b_attn = (const float*)d_in[2];
    const float* W_proj = (const float*)d_in[3];
    const float* b_proj = (const float*)d_in[4];
    float* out  = (float*)d_out;
    float* Kout = out + (size_t)YSZ;
    float* Vout = out + 2*(size_t)YSZ;

    qkv_gemm<<<dim3(3*CD/128, MROWS/128), 256>>>(x, W_attn, b_attn, Kout, Vout);

    cudaFuncSetAttribute(attn2, cudaFuncAttributeMaxDynamicSharedMemorySize,
                         (int)ATTN_SMEM);
    attn2<<<dim3(TQ/BM, BATCH*NHEAD), 256, ATTN_SMEM>>>(Kout, Vout);

    proj_gemm<<<dim3(CD/128, MROWS/128), 256>>>(W_proj, b_proj, out);
}

// round 5
// speedup vs baseline: 2.7148x; 1.4342x over previous
#include <cuda_runtime.h>
#include <cuda_bf16.h>
#include <cstdint>

// Problem constants
#define TQ    2048
#define CD    1024
#define NHEAD 16
#define HDIM  64
#define BATCH 2
#define MROWS (BATCH*TQ)        // 4096
#define YSZ   (BATCH*TQ*CD)

typedef unsigned long long u64;

// ---------------- f32x2 helpers (attention kernel) ----------------
__device__ __forceinline__ u64 splat2(float x) {
    u64 r; asm("mov.b64 %0, {%1, %1};" : "=l"(r) : "f"(x)); return r;
}
__device__ __forceinline__ void unpack2(u64 v, float &x, float &y) {
    asm("mov.b64 {%0, %1}, %2;" : "=f"(x), "=f"(y) : "l"(v));
}
__device__ __forceinline__ void ffma2(u64 &d, u64 a, u64 b) {
    asm("fma.rn.f32x2 %0, %1, %2, %0;" : "+l"(d) : "l"(a), "l"(b));
}
__device__ __forceinline__ void fmul2(u64 &d, u64 a, u64 b) {
    asm("mul.rn.f32x2 %0, %1, %2;" : "=l"(d) : "l"(a), "l"(b));
}

// ---------------- mma.sync helpers (compute_80 baseline; HMMA on sm_103) ----
__device__ __forceinline__ uint32_t smem_u32(const void* p) {
    uint32_t a;
    asm("{ .reg .u64 t; cvta.to.shared.u64 t, %1; cvt.u32.u64 %0, t; }" : "=r"(a) : "l"(p));
    return a;
}
__device__ __forceinline__ void cp_async16(uint32_t saddr, const void* g) {
    asm volatile("cp.async.cg.shared.global [%0], [%1], 16;" :: "r"(saddr), "l"(g));
}
#define CP_COMMIT() asm volatile("cp.async.commit_group;" ::: "memory")
#define CP_WAIT0()  asm volatile("cp.async.wait_group 0;" ::: "memory")
#define CP_WAIT1()  asm volatile("cp.async.wait_group 1;" ::: "memory")

__device__ __forceinline__ void ldsm_x4(uint32_t* r, uint32_t addr) {
    asm volatile("ldmatrix.sync.aligned.m8n8.x4.shared.b16 {%0,%1,%2,%3}, [%4];"
        : "=r"(r[0]), "=r"(r[1]), "=r"(r[2]), "=r"(r[3]) : "r"(addr));
}
__device__ __forceinline__ void ldsm_x2(uint32_t* r, uint32_t addr) {
    asm volatile("ldmatrix.sync.aligned.m8n8.x2.shared.b16 {%0,%1}, [%2];"
        : "=r"(r[0]), "=r"(r[1]) : "r"(addr));
}
__device__ __forceinline__ void mma_bf16(float* c, const uint32_t* a, const uint32_t* b) {
    asm volatile("mma.sync.aligned.m16n8k16.row.col.f32.bf16.bf16.f32 "
        "{%0,%1,%2,%3}, {%4,%5,%6,%7}, {%8,%9}, {%0,%1,%2,%3};"
        : "+f"(c[0]), "+f"(c[1]), "+f"(c[2]), "+f"(c[3])
        : "r"(a[0]), "r"(a[1]), "r"(a[2]), "r"(a[3]), "r"(b[0]), "r"(b[1]));
}

// ---------------- global scratch (no allocation allowed) ----------------
__device__ float g_Q[BATCH*NHEAD*TQ*HDIM];
__device__ float g_Yatt[BATCH*TQ*CD];
__device__ __nv_bfloat16 g_xh[MROWS*CD],  g_xl[MROWS*CD];
__device__ __nv_bfloat16 g_Yh[MROWS*CD],  g_Yl[MROWS*CD];
__device__ __nv_bfloat16 g_WaTh[3*CD*CD], g_WaTl[3*CD*CD];    // W_attn^T [3072,1024]
__device__ __nv_bfloat16 g_WpTh[CD*CD],   g_WpTl[CD*CD];      // W_proj^T [1024,1024]

// ---------------- split kernels ----------------
__global__ __launch_bounds__(256) void split_kernel(
    const float* __restrict__ src, __nv_bfloat16* __restrict__ hi,
    __nv_bfloat16* __restrict__ lo, int n4)
{
    int i = blockIdx.x * 256 + threadIdx.x;
    if (i >= n4) return;
    float4 v = ((const float4*)src)[i];
    __nv_bfloat16 h[4], l[4];
    float vv[4] = {v.x, v.y, v.z, v.w};
#pragma unroll
    for (int j = 0; j < 4; j++) {
        h[j] = __float2bfloat16(vv[j]);
        l[j] = __float2bfloat16(vv[j] - __bfloat162float(h[j]));
    }
    ((uint2*)hi)[i] = *(uint2*)h;
    ((uint2*)lo)[i] = *(uint2*)l;
}

__global__ __launch_bounds__(256) void tsplit_kernel(
    const float* __restrict__ W, __nv_bfloat16* __restrict__ Th,
    __nv_bfloat16* __restrict__ Tl, int K, int N)
{
    __shared__ float tile[32][33];
    int bx = blockIdx.x * 32, by = blockIdx.y * 32;
    int tx = threadIdx.x & 31, ty = threadIdx.x >> 5;
#pragma unroll
    for (int r = ty; r < 32; r += 8)
        tile[r][tx] = W[(size_t)(by + r) * N + bx + tx];
    __syncthreads();
#pragma unroll
    for (int r = ty; r < 32; r += 8) {
        float v = tile[tx][r];
        __nv_bfloat16 h = __float2bfloat16(v);
        __nv_bfloat16 l = __float2bfloat16(v - __bfloat162float(h));
        size_t o = (size_t)(bx + r) * K + by + tx;
        Th[o] = h; Tl[o] = l;
    }
}

// ---------------- mma.sync split-bf16 GEMM ----------------
// C[m,n] = sum_k A[m,k]*B[n,k] + bias[n]
// CTA 128x128, 256 threads (8 warps, warp tile 32x64), K-chunk 64, 2 stages.
// SMEM per stage: Ah|Al|Bh|Bl tiles, each [128][64] bf16 = 16KB, SW128 swizzle.
#define TILE_SZ   16384
#define STAGE_SZ  (4*TILE_SZ)      // 64KB
#define GEMM_SMEM (2*STAGE_SZ)     // 128KB

__global__ __launch_bounds__(256) void mma_gemm(
    const __nv_bfloat16* __restrict__ Ah, const __nv_bfloat16* __restrict__ Al,
    const __nv_bfloat16* __restrict__ Bh, const __nv_bfloat16* __restrict__ Bl,
    const float* __restrict__ bias, int mode,
    float* __restrict__ out, float* __restrict__ Kout, float* __restrict__ Vout)
{
    extern __shared__ __align__(1024) char sm[];
    const uint32_t sb = smem_u32(sm);
    const int tid = threadIdx.x, lane = tid & 31, wid = tid >> 5;
    const int wm = wid & 3, wn = wid >> 2;            // warp tile (wm*32, wn*64)
    const int m0 = blockIdx.y * 128, n0 = blockIdx.x * 128;

    // loader precompute: each thread loads 4x 16B per tile per chunk
    int lr[4], lsw[4];
#pragma unroll
    for (int p = 0; p < 4; p++) {
        int i = tid + p * 256;                  // 0..1023
        int r = i >> 3, c = i & 7;
        lr[p] = r;
        lsw[p] = r * 128 + ((c ^ (r & 7)) << 4);
    }

#define LOAD_CHUNK(kc, stage) do {                                          \
        uint32_t s0 = sb + (stage) * STAGE_SZ;                              \
        int kcol = (kc) * 64;                                               \
        _Pragma("unroll")                                                   \
        for (int p = 0; p < 4; p++) {                                       \
            int c8 = ((tid + p*256) & 7) * 8;                               \
            size_t ga = (size_t)(m0 + lr[p]) * CD + kcol + c8;              \
            size_t gb = (size_t)(n0 + lr[p]) * CD + kcol + c8;              \
            cp_async16(s0 + 0*TILE_SZ + lsw[p], Ah + ga);                   \
            cp_async16(s0 + 1*TILE_SZ + lsw[p], Al + ga);                   \
            cp_async16(s0 + 2*TILE_SZ + lsw[p], Bh + gb);                   \
            cp_async16(s0 + 3*TILE_SZ + lsw[p], Bl + gb);                   \
        }                                                                   \
    } while (0)

    float C[2][8][4];
#pragma unroll
    for (int mi = 0; mi < 2; mi++)
#pragma unroll
        for (int ni = 0; ni < 8; ni++)
#pragma unroll
            for (int q = 0; q < 4; q++) C[mi][ni][q] = 0.f;

    // ldmatrix address components
    const int ar  = wm*32 + (lane & 15);        // A row (+16 for mi=1)
    const int ach = (lane >> 4);                // A k-chunk sub (0/1)
    const int br  = wn*64 + (lane & 7);         // B row (+8*ni)
    const int bch = ((lane >> 3) & 1);          // B k-chunk sub

    LOAD_CHUNK(0, 0); CP_COMMIT();
    LOAD_CHUNK(1, 1); CP_COMMIT();

    for (int kc = 0; kc < 16; kc++) {
        if (kc == 15) { CP_WAIT0(); } else { CP_WAIT1(); }
        __syncthreads();
        const uint32_t s0 = sb + (kc & 1) * STAGE_SZ;
        const uint32_t tAh = s0, tAl = s0 + TILE_SZ;
        const uint32_t tBh = s0 + 2*TILE_SZ, tBl = s0 + 3*TILE_SZ;

#pragma unroll
        for (int ks = 0; ks < 4; ks++) {
            uint32_t aH[2][4], aL[2][4];
#pragma unroll
            for (int mi = 0; mi < 2; mi++) {
                int r = ar + mi*16;
                int c = ks*2 + ach;
                uint32_t off = r*128 + ((c ^ (r & 7)) << 4);
                ldsm_x4(aH[mi], tAh + off);
                ldsm_x4(aL[mi], tAl + off);
            }
#pragma unroll
            for (int ni = 0; ni < 8; ni += 2) {
                uint32_t bH0[2], bL0[2], bH1[2], bL1[2];
                {
                    int r = br + ni*8;
                    int c = ks*2 + bch;
                    uint32_t off = r*128 + ((c ^ (r & 7)) << 4);
                    ldsm_x2(bH0, tBh + off);
                    ldsm_x2(bL0, tBl + off);
                }
                {
                    int r = br + (ni+1)*8;
                    int c = ks*2 + bch;
                    uint32_t off = r*128 + ((c ^ (r & 7)) << 4);
                    ldsm_x2(bH1, tBh + off);
                    ldsm_x2(bL1, tBl + off);
                }
                // 12 mma, 4 independent accumulation chains
                mma_bf16(C[0][ni],   aH[0], bH0);
                mma_bf16(C[1][ni],   aH[1], bH0);
                mma_bf16(C[0][ni+1], aH[0], bH1);
                mma_bf16(C[1][ni+1], aH[1], bH1);
                mma_bf16(C[0][ni],   aH[0], bL0);
                mma_bf16(C[1][ni],   aH[1], bL0);
                mma_bf16(C[0][ni+1], aH[0], bL1);
                mma_bf16(C[1][ni+1], aH[1], bL1);
                mma_bf16(C[0][ni],   aL[0], bH0);
                mma_bf16(C[1][ni],   aL[1], bH0);
                mma_bf16(C[0][ni+1], aL[0], bH1);
                mma_bf16(C[1][ni+1], aL[1], bH1);
            }
        }
        __syncthreads();
        if (kc + 2 < 16) { LOAD_CHUNK(kc + 2, kc & 1); CP_COMMIT(); }
    }

    // Epilogue: thread holds C[mi][ni][{c0,c1 @ m; c2,c3 @ m+8}], n = 2*(lane&3)
    const int mbase = m0 + wm*32 + (lane >> 2);
    const int npair = 2*(lane & 3);
#pragma unroll
    for (int mi = 0; mi < 2; mi++) {
#pragma unroll
        for (int half = 0; half < 2; half++) {
            int m = mbase + mi*16 + half*8;
            int b = m >> 11, tt = m & (TQ - 1);
#pragma unroll
            for (int ni = 0; ni < 8; ni++) {
                int n = n0 + wn*64 + ni*8 + npair;
                float2 bv = *(const float2*)(bias + n);
                float2 v;
                v.x = C[mi][ni][half*2+0] + bv.x;
                v.y = C[mi][ni][half*2+1] + bv.y;
                if (mode == 0) {
                    int sec = n >> 10, within = n & 1023;
                    int h = within >> 6, dd = within & 63;
                    size_t idx = ((size_t)(b*NHEAD + h)*TQ + tt)*HDIM + dd;
                    float* dst = (sec == 0) ? g_Q : (sec == 1 ? Kout : Vout);
                    *(float2*)(dst + idx) = v;
                } else {
                    *(float2*)(out + (size_t)m*CD + n) = v;
                }
            }
        }
    }
#undef LOAD_CHUNK
}

// ---------------------------------------------------------------------------
// Flash attention (f32x2 SIMT) — unchanged from R3
// ---------------------------------------------------------------------------
#define BM 128
#define BN 128
#define LDT 132
#define LDV 68
#define LDP 132
#define ATTN_SMEM ((64*LDT*2 + BN*LDV + BM*LDP + 2*BM) * sizeof(float))

__global__ __launch_bounds__(256) void attn2(
    const float* __restrict__ Kg, const float* __restrict__ Vg)
{
    extern __shared__ float smf[];
    float* Qt = smf;
    float* Kt = Qt + 64*LDT;
    float* Vs = Kt + 64*LDT;
    float* Ps = Vs + BN*LDV;
    float* aB = Ps + (size_t)BM*LDP;
    float* lB = aB + BM;

    const int bh = blockIdx.y;
    const int qb = gridDim.x - 1 - blockIdx.x;
    const int q0 = qb * BM;
    const int t  = threadIdx.x;
    const int ty = t >> 4, tx = t & 15;
    const int g  = t >> 3, ec = (t & 7) * 8;

    const float* Qb = g_Q + ((size_t)bh*TQ + q0) * HDIM;
    for (int i = t; i < BM*16; i += 256) {
        int m = i >> 4, dq = (i & 15) << 2;
        float4 v = *(const float4*)(Qb + m*HDIM + dq);
        Qt[(dq+0)*LDT + m] = v.x * 0.125f;
        Qt[(dq+1)*LDT + m] = v.y * 0.125f;
        Qt[(dq+2)*LDT + m] = v.z * 0.125f;
        Qt[(dq+3)*LDT + m] = v.w * 0.125f;
    }

    float row_m[8], row_l[8];
#pragma unroll
    for (int i = 0; i < 8; i++) { row_m[i] = -1e30f; row_l[i] = 0.f; }
    u64 O2[4][4];
#pragma unroll
    for (int i = 0; i < 4; i++)
#pragma unroll
        for (int c = 0; c < 4; c++) O2[i][c] = 0ULL;

    for (int kb = 0; kb <= qb; kb++) {
        const int k0 = kb * BN;
        const float* Kb = Kg + ((size_t)bh*TQ + k0) * HDIM;
        const float* Vb = Vg + ((size_t)bh*TQ + k0) * HDIM;
        for (int i = t; i < BN*16; i += 256) {
            int n = i >> 4, dq = (i & 15) << 2;
            float4 kv = *(const float4*)(Kb + n*HDIM + dq);
            Kt[(dq+0)*LDT + n] = kv.x;
            Kt[(dq+1)*LDT + n] = kv.y;
            Kt[(dq+2)*LDT + n] = kv.z;
            Kt[(dq+3)*LDT + n] = kv.w;
            *(float4*)(Vs + n*LDV + dq) = *(const float4*)(Vb + n*HDIM + dq);
        }
        __syncthreads();

        u64 S2[8][4];
#pragma unroll
        for (int i = 0; i < 8; i++)
#pragma unroll
            for (int jp = 0; jp < 4; jp++) S2[i][jp] = 0ULL;

#pragma unroll 4
        for (int d = 0; d < HDIM; d++) {
            float a[8];
            *(float4*)(a)   = *(const float4*)(Qt + d*LDT + ty*8);
            *(float4*)(a+4) = *(const float4*)(Qt + d*LDT + ty*8 + 4);
            const u64* bp = (const u64*)(Kt + d*LDT + tx*8);
            u64 b0 = bp[0], b1 = bp[1], b2 = bp[2], b3 = bp[3];
#pragma unroll
            for (int i = 0; i < 8; i++) {
                u64 sa = splat2(a[i]);
                ffma2(S2[i][0], sa, b0);
                ffma2(S2[i][1], sa, b1);
                ffma2(S2[i][2], sa, b2);
                ffma2(S2[i][3], sa, b3);
            }
        }

        const bool diag = (kb == qb);
#pragma unroll
        for (int i = 0; i < 8; i++) {
            float v[8];
            unpack2(S2[i][0], v[0], v[1]);
            unpack2(S2[i][1], v[2], v[3]);
            unpack2(S2[i][2], v[4], v[5]);
            unpack2(S2[i][3], v[6], v[7]);
            const int r = ty*8 + i;
            if (diag) {
#pragma unroll
                for (int j = 0; j < 8; j++)
                    if (tx*8 + j > r) v[j] = -1e30f;
            }
            float mx = v[0];
#pragma unroll
            for (int j = 1; j < 8; j++) mx = fmaxf(mx, v[j]);
            mx = fmaxf(mx, __shfl_xor_sync(0xffffffffu, mx, 1));
            mx = fmaxf(mx, __shfl_xor_sync(0xffffffffu, mx, 2));
            mx = fmaxf(mx, __shfl_xor_sync(0xffffffffu, mx, 4));
            mx = fmaxf(mx, __shfl_xor_sync(0xffffffffu, mx, 8));
            float mnew = fmaxf(row_m[i], mx);
            float al   = __expf(row_m[i] - mnew);
            float s = 0.f;
#pragma unroll
            for (int j = 0; j < 8; j++) {
                v[j] = __expf(v[j] - mnew);
                s += v[j];
            }
            s += __shfl_xor_sync(0xffffffffu, s, 1);
            s += __shfl_xor_sync(0xffffffffu, s, 2);
            s += __shfl_xor_sync(0xffffffffu, s, 4);
            s += __shfl_xor_sync(0xffffffffu, s, 8);
            row_l[i] = row_l[i] * al + s;
            row_m[i] = mnew;
            if (tx == 0) aB[r] = al;
            *(float4*)(Ps + (size_t)r*LDP + tx*8)     = make_float4(v[0], v[1], v[2], v[3]);
            *(float4*)(Ps + (size_t)r*LDP + tx*8 + 4) = make_float4(v[4], v[5], v[6], v[7]);
        }
        __syncthreads();

#pragma unroll
        for (int i = 0; i < 4; i++) {
            u64 al2 = splat2(aB[g*4 + i]);
            fmul2(O2[i][0], O2[i][0], al2);
            fmul2(O2[i][1], O2[i][1], al2);
            fmul2(O2[i][2], O2[i][2], al2);
            fmul2(O2[i][3], O2[i][3], al2);
        }
#pragma unroll 2
        for (int j = 0; j < BN; j += 2) {
            const u64* vpa = (const u64*)(Vs + j*LDV + ec);
            const u64* vpb = (const u64*)(Vs + (j+1)*LDV + ec);
            u64 va0 = vpa[0], va1 = vpa[1], va2 = vpa[2], va3 = vpa[3];
            u64 vb0 = vpb[0], vb1 = vpb[1], vb2 = vpb[2], vb3 = vpb[3];
#pragma unroll
            for (int i = 0; i < 4; i++) {
                u64 p2 = *(const u64*)(Ps + (size_t)(g*4+i)*LDP + j);
                float plo, phi;
                unpack2(p2, plo, phi);
                u64 sl = splat2(plo), sh = splat2(phi);
                ffma2(O2[i][0], sl, va0);
                ffma2(O2[i][1], sl, va1);
                ffma2(O2[i][2], sl, va2);
                ffma2(O2[i][3], sl, va3);
                ffma2(O2[i][0], sh, vb0);
                ffma2(O2[i][1], sh, vb1);
                ffma2(O2[i][2], sh, vb2);
                ffma2(O2[i][3], sh, vb3);
            }
        }
        __syncthreads();
    }

    if (tx == 0) {
#pragma unroll
        for (int i = 0; i < 8; i++) lB[ty*8 + i] = 1.f / row_l[i];
    }
    __syncthreads();

    const int b = bh >> 4, h = bh & 15;
#pragma unroll
    for (int i = 0; i < 4; i++) {
        float inv = lB[g*4 + i];
        float o[8];
        unpack2(O2[i][0], o[0], o[1]);
        unpack2(O2[i][1], o[2], o[3]);
        unpack2(O2[i][2], o[4], o[5]);
        unpack2(O2[i][3], o[6], o[7]);
        float* yp = g_Yatt + ((size_t)(b*TQ + q0 + g*4 + i))*CD + h*HDIM + ec;
        *(float4*)(yp)     = make_float4(o[0]*inv, o[1]*inv, o[2]*inv, o[3]*inv);
        *(float4*)(yp + 4) = make_float4(o[4]*inv, o[5]*inv, o[6]*inv, o[7]*inv);
    }
}

// ---------------------------------------------------------------------------
extern "C" void kernel_launch(void* const* d_in, const int* in_sizes, int n_in,
                              void* d_out, int out_size)
{
    const float* x      = (const float*)d_in[0];
    const float* W_attn = (const float*)d_in[1];
    const float* b_attn = (const float*)d_in[2];
    const float* W_proj = (const float*)d_in[3];
    const float* b_proj = (const float*)d_in[4];
    float* out  = (float*)d_out;
    float* Kout = out + (size_t)YSZ;
    float* Vout = out + 2*(size_t)YSZ;

    __nv_bfloat16 *xh, *xl, *Yh, *Yl, *WaTh, *WaTl, *WpTh, *WpTl;
    float *Yattg;
    cudaGetSymbolAddress((void**)&xh,   g_xh);
    cudaGetSymbolAddress((void**)&xl,   g_xl);
    cudaGetSymbolAddress((void**)&Yh,   g_Yh);
    cudaGetSymbolAddress((void**)&Yl,   g_Yl);
    cudaGetSymbolAddress((void**)&WaTh, g_WaTh);
    cudaGetSymbolAddress((void**)&WaTl, g_WaTl);
    cudaGetSymbolAddress((void**)&WpTh, g_WpTh);
    cudaGetSymbolAddress((void**)&WpTl, g_WpTl);
    cudaGetSymbolAddress((void**)&Yattg, g_Yatt);

    static int attr_done = 0;
    if (!attr_done) {
        cudaFuncSetAttribute(attn2, cudaFuncAttributeMaxDynamicSharedMemorySize, (int)ATTN_SMEM);
        cudaFuncSetAttribute(mma_gemm, cudaFuncAttributeMaxDynamicSharedMemorySize, GEMM_SMEM);
        attr_done = 1;
    }

    // 1) split inputs to hi/lo bf16
    split_kernel<<<(MROWS*CD/4 + 255)/256, 256>>>(x, xh, xl, MROWS*CD/4);
    tsplit_kernel<<<dim3(3*CD/32, CD/32), 256>>>(W_attn, WaTh, WaTl, CD, 3*CD);
    tsplit_kernel<<<dim3(CD/32, CD/32), 256>>>(W_proj, WpTh, WpTl, CD, CD);

    // 2) qkv = x @ W_attn + b  (HMMA split-bf16) -> Q scratch + K/V out
    mma_gemm<<<dim3(3*CD/128, MROWS/128), 256, GEMM_SMEM>>>(
        xh, xl, WaTh, WaTl, b_attn, 0, nullptr, Kout, Vout);

    // 3) causal flash attention
    attn2<<<dim3(TQ/BM, BATCH*NHEAD), 256, ATTN_SMEM>>>(Kout, Vout);

    // 4) split attention output, then proj GEMM
    split_kernel<<<(MROWS*CD/4 + 255)/256, 256>>>(Yattg, Yh, Yl, MROWS*CD/4);
    mma_gemm<<<dim3(CD/128, MROWS/128), 256, GEMM_SMEM>>>(
        Yh, Yl, WpTh, WpTl, b_proj, 1, out, nullptr, nullptr);
}

// round 6
// speedup vs baseline: 6.6533x; 2.4507x over previous
#include <cuda_runtime.h>
#include <cuda_bf16.h>
#include <cuda_fp16.h>
#include <cstdint>

// Problem constants
#define TQ    2048
#define CD    1024
#define NHEAD 16
#define HDIM  64
#define BATCH 2
#define MROWS (BATCH*TQ)        // 4096
#define YSZ   (BATCH*TQ*CD)

// ---------------- mma.sync helpers (compute_80 baseline; HMMA on sm_103) ----
__device__ __forceinline__ uint32_t smem_u32(const void* p) {
    uint32_t a;
    asm("{ .reg .u64 t; cvta.to.shared.u64 t, %1; cvt.u32.u64 %0, t; }" : "=r"(a) : "l"(p));
    return a;
}
__device__ __forceinline__ void cp_async16(uint32_t saddr, const void* g) {
    asm volatile("cp.async.cg.shared.global [%0], [%1], 16;" :: "r"(saddr), "l"(g));
}
#define CP_COMMIT() asm volatile("cp.async.commit_group;" ::: "memory")
#define CP_WAIT0()  asm volatile("cp.async.wait_group 0;" ::: "memory")
#define CP_WAIT1()  asm volatile("cp.async.wait_group 1;" ::: "memory")

__device__ __forceinline__ void ldsm_x4(uint32_t* r, uint32_t addr) {
    asm volatile("ldmatrix.sync.aligned.m8n8.x4.shared.b16 {%0,%1,%2,%3}, [%4];"
        : "=r"(r[0]), "=r"(r[1]), "=r"(r[2]), "=r"(r[3]) : "r"(addr));
}
__device__ __forceinline__ void ldsm_x2(uint32_t* r, uint32_t addr) {
    asm volatile("ldmatrix.sync.aligned.m8n8.x2.shared.b16 {%0,%1}, [%2];"
        : "=r"(r[0]), "=r"(r[1]) : "r"(addr));
}
__device__ __forceinline__ void ldsm_x4_t(uint32_t* r, uint32_t addr) {
    asm volatile("ldmatrix.sync.aligned.m8n8.x4.trans.shared.b16 {%0,%1,%2,%3}, [%4];"
        : "=r"(r[0]), "=r"(r[1]), "=r"(r[2]), "=r"(r[3]) : "r"(addr));
}
__device__ __forceinline__ void mma_bf16(float* c, const uint32_t* a, const uint32_t* b) {
    asm volatile("mma.sync.aligned.m16n8k16.row.col.f32.bf16.bf16.f32 "
        "{%0,%1,%2,%3}, {%4,%5,%6,%7}, {%8,%9}, {%0,%1,%2,%3};"
        : "+f"(c[0]), "+f"(c[1]), "+f"(c[2]), "+f"(c[3])
        : "r"(a[0]), "r"(a[1]), "r"(a[2]), "r"(a[3]), "r"(b[0]), "r"(b[1]));
}
__device__ __forceinline__ void mma_f16(float* c, const uint32_t* a, const uint32_t* b) {
    asm volatile("mma.sync.aligned.m16n8k16.row.col.f32.f16.f16.f32 "
        "{%0,%1,%2,%3}, {%4,%5,%6,%7}, {%8,%9}, {%0,%1,%2,%3};"
        : "+f"(c[0]), "+f"(c[1]), "+f"(c[2]), "+f"(c[3])
        : "r"(a[0]), "r"(a[1]), "r"(a[2]), "r"(a[3]), "r"(b[0]), "r"(b[1]));
}
// pack (lo, hi) floats -> f16x2 register (lo in low half)
__device__ __forceinline__ uint32_t f16pair(float lo, float hi) {
    uint32_t d;
    asm("cvt.rn.f16x2.f32 %0, %1, %2;" : "=r"(d) : "f"(hi), "f"(lo));
    return d;
}
// split (x,y) into hi/lo bf16 pairs packed as u32 (x in low half)
__device__ __forceinline__ void bf16split2(float x, float y, uint32_t& hi, uint32_t& lo) {
    __nv_bfloat162 h = __floats2bfloat162_rn(x, y);
    float hx = __bfloat162float(__low2bfloat16(h));
    float hy = __bfloat162float(__high2bfloat16(h));
    __nv_bfloat162 l = __floats2bfloat162_rn(x - hx, y - hy);
    hi = *(uint32_t*)&h;
    lo = *(uint32_t*)&l;
}

// ---------------- global scratch (no allocation allowed) ----------------
__device__ __nv_bfloat16 g_Qbh[BATCH*NHEAD*TQ*HDIM], g_Qbl[BATCH*NHEAD*TQ*HDIM];
__device__ __nv_bfloat16 g_Kbh[BATCH*NHEAD*TQ*HDIM], g_Kbl[BATCH*NHEAD*TQ*HDIM];
__device__ __half        g_Vhf[BATCH*NHEAD*TQ*HDIM];
__device__ __nv_bfloat16 g_xh[MROWS*CD],  g_xl[MROWS*CD];
__device__ __nv_bfloat16 g_Yh[MROWS*CD],  g_Yl[MROWS*CD];
__device__ __nv_bfloat16 g_WaTh[3*CD*CD], g_WaTl[3*CD*CD];    // W_attn^T [3072,1024]
__device__ __nv_bfloat16 g_WpTh[CD*CD],   g_WpTl[CD*CD];      // W_proj^T [1024,1024]

// ---------------- split kernels ----------------
__global__ __launch_bounds__(256) void split_kernel(
    const float* __restrict__ src, __nv_bfloat16* __restrict__ hi,
    __nv_bfloat16* __restrict__ lo, int n4)
{
    int i = blockIdx.x * 256 + threadIdx.x;
    if (i >= n4) return;
    float4 v = ((const float4*)src)[i];
    __nv_bfloat16 h[4], l[4];
    float vv[4] = {v.x, v.y, v.z, v.w};
#pragma unroll
    for (int j = 0; j < 4; j++) {
        h[j] = __float2bfloat16(vv[j]);
        l[j] = __float2bfloat16(vv[j] - __bfloat162float(h[j]));
    }
    ((uint2*)hi)[i] = *(uint2*)h;
    ((uint2*)lo)[i] = *(uint2*)l;
}

__global__ __launch_bounds__(256) void tsplit_kernel(
    const float* __restrict__ W, __nv_bfloat16* __restrict__ Th,
    __nv_bfloat16* __restrict__ Tl, int K, int N)
{
    __shared__ float tile[32][33];
    int bx = blockIdx.x * 32, by = blockIdx.y * 32;
    int tx = threadIdx.x & 31, ty = threadIdx.x >> 5;
#pragma unroll
    for (int r = ty; r < 32; r += 8)
        tile[r][tx] = W[(size_t)(by + r) * N + bx + tx];
    __syncthreads();
#pragma unroll
    for (int r = ty; r < 32; r += 8) {
        float v = tile[tx][r];
        __nv_bfloat16 h = __float2bfloat16(v);
        __nv_bfloat16 l = __float2bfloat16(v - __bfloat162float(h));
        size_t o = (size_t)(bx + r) * K + by + tx;
        Th[o] = h; Tl[o] = l;
    }
}

// ---------------- mma.sync split-bf16 GEMM ----------------
#define TILE_SZ   16384
#define STAGE_SZ  (4*TILE_SZ)      // 64KB
#define GEMM_SMEM (2*STAGE_SZ)     // 128KB

__global__ __launch_bounds__(256) void mma_gemm(
    const __nv_bfloat16* __restrict__ Ah, const __nv_bfloat16* __restrict__ Al,
    const __nv_bfloat16* __restrict__ Bh, const __nv_bfloat16* __restrict__ Bl,
    const float* __restrict__ bias, int mode,
    float* __restrict__ out, float* __restrict__ Kout, float* __restrict__ Vout)
{
    extern __shared__ __align__(1024) char sm[];
    const uint32_t sb = smem_u32(sm);
    const int tid = threadIdx.x, lane = tid & 31, wid = tid >> 5;
    const int wm = wid & 3, wn = wid >> 2;
    const int m0 = blockIdx.y * 128, n0 = blockIdx.x * 128;

    int lr[4], lsw[4];
#pragma unroll
    for (int p = 0; p < 4; p++) {
        int i = tid + p * 256;
        int r = i >> 3, c = i & 7;
        lr[p] = r;
        lsw[p] = r * 128 + ((c ^ (r & 7)) << 4);
    }

#define LOAD_CHUNK(kc, stage) do {                                          \
        uint32_t s0 = sb + (stage) * STAGE_SZ;                              \
        int kcol = (kc) * 64;                                               \
        _Pragma("unroll")                                                   \
        for (int p = 0; p < 4; p++) {                                       \
            int c8 = ((tid + p*256) & 7) * 8;                               \
            size_t ga = (size_t)(m0 + lr[p]) * CD + kcol + c8;              \
            size_t gb = (size_t)(n0 + lr[p]) * CD + kcol + c8;              \
            cp_async16(s0 + 0*TILE_SZ + lsw[p], Ah + ga);                   \
            cp_async16(s0 + 1*TILE_SZ + lsw[p], Al + ga);                   \
            cp_async16(s0 + 2*TILE_SZ + lsw[p], Bh + gb);                   \
            cp_async16(s0 + 3*TILE_SZ + lsw[p], Bl + gb);                   \
        }                                                                   \
    } while (0)

    float C[2][8][4];
#pragma unroll
    for (int mi = 0; mi < 2; mi++)
#pragma unroll
        for (int ni = 0; ni < 8; ni++)
#pragma unroll
            for (int q = 0; q < 4; q++) C[mi][ni][q] = 0.f;

    const int ar  = wm*32 + (lane & 15);
    const int ach = (lane >> 4);
    const int br  = wn*64 + (lane & 7);
    const int bch = ((lane >> 3) & 1);

    LOAD_CHUNK(0, 0); CP_COMMIT();
    LOAD_CHUNK(1, 1); CP_COMMIT();

    for (int kc = 0; kc < 16; kc++) {
        if (kc == 15) { CP_WAIT0(); } else { CP_WAIT1(); }
        __syncthreads();
        const uint32_t s0 = sb + (kc & 1) * STAGE_SZ;
        const uint32_t tAh = s0, tAl = s0 + TILE_SZ;
        const uint32_t tBh = s0 + 2*TILE_SZ, tBl = s0 + 3*TILE_SZ;

#pragma unroll
        for (int ks = 0; ks < 4; ks++) {
            uint32_t aH[2][4], aL[2][4];
#pragma unroll
            for (int mi = 0; mi < 2; mi++) {
                int r = ar + mi*16;
                int c = ks*2 + ach;
                uint32_t off = r*128 + ((c ^ (r & 7)) << 4);
                ldsm_x4(aH[mi], tAh + off);
                ldsm_x4(aL[mi], tAl + off);
            }
#pragma unroll
            for (int ni = 0; ni < 8; ni += 2) {
                uint32_t bH0[2], bL0[2], bH1[2], bL1[2];
                {
                    int r = br + ni*8;
                    int c = ks*2 + bch;
                    uint32_t off = r*128 + ((c ^ (r & 7)) << 4);
                    ldsm_x2(bH0, tBh + off);
                    ldsm_x2(bL0, tBl + off);
                }
                {
                    int r = br + (ni+1)*8;
                    int c = ks*2 + bch;
                    uint32_t off = r*128 + ((c ^ (r & 7)) << 4);
                    ldsm_x2(bH1, tBh + off);
                    ldsm_x2(bL1, tBl + off);
                }
                mma_bf16(C[0][ni],   aH[0], bH0);
                mma_bf16(C[1][ni],   aH[1], bH0);
                mma_bf16(C[0][ni+1], aH[0], bH1);
                mma_bf16(C[1][ni+1], aH[1], bH1);
                mma_bf16(C[0][ni],   aH[0], bL0);
                mma_bf16(C[1][ni],   aH[1], bL0);
                mma_bf16(C[0][ni+1], aH[0], bL1);
                mma_bf16(C[1][ni+1], aH[1], bL1);
                mma_bf16(C[0][ni],   aL[0], bH0);
                mma_bf16(C[1][ni],   aL[1], bH0);
                mma_bf16(C[0][ni+1], aL[0], bH1);
                mma_bf16(C[1][ni+1], aL[1], bH1);
            }
        }
        __syncthreads();
        if (kc + 2 < 16) { LOAD_CHUNK(kc + 2, kc & 1); CP_COMMIT(); }
    }

    // Epilogue
    const int mbase = m0 + wm*32 + (lane >> 2);
    const int npair = 2*(lane & 3);
#pragma unroll
    for (int mi = 0; mi < 2; mi++) {
#pragma unroll
        for (int half = 0; half < 2; half++) {
            int m = mbase + mi*16 + half*8;
            int b = m >> 11, tt = m & (TQ - 1);
#pragma unroll
            for (int ni = 0; ni < 8; ni++) {
                int n = n0 + wn*64 + ni*8 + npair;
                float2 bv = *(const float2*)(bias + n);
                float2 v;
                v.x = C[mi][ni][half*2+0] + bv.x;
                v.y = C[mi][ni][half*2+1] + bv.y;
                if (mode == 0) {
                    int sec = n >> 10, within = n & 1023;
                    int h = within >> 6, dd = within & 63;
                    size_t idx = ((size_t)(b*NHEAD + h)*TQ + tt)*HDIM + dd;
                    if (sec == 0) {
                        // Q: fold in 1/sqrt(hd), store bf16 hi/lo
                        uint32_t hi, lo;
                        bf16split2(v.x * 0.125f, v.y * 0.125f, hi, lo);
                        *(uint32_t*)(g_Qbh + idx) = hi;
                        *(uint32_t*)(g_Qbl + idx) = lo;
                    } else if (sec == 1) {
                        *(float2*)(Kout + idx) = v;     // present_k output
                        uint32_t hi, lo;
                        bf16split2(v.x, v.y, hi, lo);
                        *(uint32_t*)(g_Kbh + idx) = hi;
                        *(uint32_t*)(g_Kbl + idx) = lo;
                    } else {
                        *(float2*)(Vout + idx) = v;     // present_v output
                        __half2 hv = __floats2half2_rn(v.x, v.y);
                        *(__half2*)(g_Vhf + idx) = hv;
                    }
                } else {
                    *(float2*)(out + (size_t)m*CD + n) = v;
                }
            }
        }
    }
#undef LOAD_CHUNK
}

// ---------------------------------------------------------------------------
// Tensor-core flash attention: CTA = 64 q-rows (4 warps x 16), key blocks of 128.
// S = QK^T bf16 3-term split; softmax in registers; PV fp16 single-term.
// Output written directly as bf16 hi/lo for the proj GEMM.
// ---------------------------------------------------------------------------
#define AT_STAGE 49152                 // Kh(16K) | Kl(16K) | V fp16(16K)
#define ATTN_SMEM (2*AT_STAGE)         // 96KB -> 2 CTAs/SM

__global__ __launch_bounds__(128) void attn3(
    const __nv_bfloat16* __restrict__ Qh, const __nv_bfloat16* __restrict__ Ql,
    const __nv_bfloat16* __restrict__ Kh, const __nv_bfloat16* __restrict__ Kl,
    const __half* __restrict__ Vf,
    __nv_bfloat16* __restrict__ Yh, __nv_bfloat16* __restrict__ Yl)
{
    extern __shared__ __align__(1024) char sm[];
    const uint32_t sb = smem_u32(sm);
    const int tid = threadIdx.x, lane = tid & 31, w = tid >> 5;
    const int bh = blockIdx.y;
    const int qt = gridDim.x - 1 - blockIdx.x;   // big tiles first
    const int q0 = qt * 64;
    const int nkb = (q0 + 191) >> 7;
    const size_t qbase = (size_t)bh * TQ;

    // Resident Q A-fragments (hi/lo), loaded directly from gmem
    const int r0 = q0 + w*16 + (lane >> 2);
    uint32_t aQh[4][4], aQl[4][4];
#pragma unroll
    for (int ks = 0; ks < 4; ks++) {
        int k = ks*16 + 2*(lane & 3);
        aQh[ks][0] = *(const uint32_t*)(Qh + (qbase + r0    )*HDIM + k);
        aQh[ks][1] = *(const uint32_t*)(Qh + (qbase + r0 + 8)*HDIM + k);
        aQh[ks][2] = *(const uint32_t*)(Qh + (qbase + r0    )*HDIM + k + 8);
        aQh[ks][3] = *(const uint32_t*)(Qh + (qbase + r0 + 8)*HDIM + k + 8);
        aQl[ks][0] = *(const uint32_t*)(Ql + (qbase + r0    )*HDIM + k);
        aQl[ks][1] = *(const uint32_t*)(Ql + (qbase + r0 + 8)*HDIM + k);
        aQl[ks][2] = *(const uint32_t*)(Ql + (qbase + r0    )*HDIM + k + 8);
        aQl[ks][3] = *(const uint32_t*)(Ql + (qbase + r0 + 8)*HDIM + k + 8);
    }

#define AT_LOAD(kb, s) do {                                                  \
        uint32_t s0 = sb + (s) * AT_STAGE;                                   \
        int k0 = (kb) * 128;                                                 \
        _Pragma("unroll")                                                    \
        for (int p = 0; p < 8; p++) {                                        \
            int i = tid + p * 128;                                           \
            int r = i >> 3, c = i & 7;                                       \
            uint32_t sw = r*128 + ((c ^ (r & 7)) << 4);                      \
            size_t g = (qbase + k0 + r) * HDIM + c*8;                        \
            cp_async16(s0 +         sw, Kh + g);                             \
            cp_async16(s0 + 16384 + sw, Kl + g);                             \
            cp_async16(s0 + 32768 + sw, Vf + g);                             \
        }                                                                    \
    } while (0)

    float m0 = -1e30f, m1 = -1e30f, l0 = 0.f, l1 = 0.f;
    float O[8][4];
#pragma unroll
    for (int nj = 0; nj < 8; nj++)
#pragma unroll
        for (int q = 0; q < 4; q++) O[nj][q] = 0.f;

    AT_LOAD(0, 0); CP_COMMIT();

    for (int kb = 0; kb < nkb; kb++) {
        const bool more = (kb + 1 < nkb);
        if (more) { AT_LOAD(kb + 1, (kb + 1) & 1); CP_COMMIT(); }
        if (more) { CP_WAIT1(); } else { CP_WAIT0(); }
        __syncthreads();
        const uint32_t s0 = sb + (kb & 1) * AT_STAGE;
        const uint32_t tKH = s0, tKL = s0 + 16384, tV = s0 + 32768;

        // ---- S = Q K^T (3-term split bf16), 16 n-tiles of 8 keys ----
        float C[16][4];
#pragma unroll
        for (int nj = 0; nj < 16; nj++)
#pragma unroll
            for (int q = 0; q < 4; q++) C[nj][q] = 0.f;

#pragma unroll
        for (int ks = 0; ks < 4; ks++) {
#pragma unroll
            for (int nj = 0; nj < 16; nj += 2) {
                uint32_t bh2[4], bl2[4];
                int mm = lane >> 3;
                int row = nj*8 + (mm >> 1)*8 + (lane & 7);
                int ch  = 2*ks + (mm & 1);
                uint32_t off = row*128 + ((ch ^ (row & 7)) << 4);
                ldsm_x4(bh2, tKH + off);
                ldsm_x4(bl2, tKL + off);
                mma_bf16(C[nj],   aQh[ks], bh2);
                mma_bf16(C[nj+1], aQh[ks], bh2 + 2);
                mma_bf16(C[nj],   aQh[ks], bl2);
                mma_bf16(C[nj+1], aQh[ks], bl2 + 2);
                mma_bf16(C[nj],   aQl[ks], bh2);
                mma_bf16(C[nj+1], aQl[ks], bh2 + 2);
            }
        }

        // ---- causal mask (last block only) ----
        if (kb == nkb - 1) {
#pragma unroll
            for (int nj = 0; nj < 16; nj++) {
                int col = kb*128 + nj*8 + 2*(lane & 3);
                if (col     > r0    ) C[nj][0] = -1e30f;
                if (col + 1 > r0    ) C[nj][1] = -1e30f;
                if (col     > r0 + 8) C[nj][2] = -1e30f;
                if (col + 1 > r0 + 8) C[nj][3] = -1e30f;
            }
        }

        // ---- online softmax (rows r0 and r0+8 per thread, quad-shuffle) ----
        float mx0 = -1e30f, mx1 = -1e30f;
#pragma unroll
        for (int nj = 0; nj < 16; nj++) {
            mx0 = fmaxf(mx0, fmaxf(C[nj][0], C[nj][1]));
            mx1 = fmaxf(mx1, fmaxf(C[nj][2], C[nj][3]));
        }
        mx0 = fmaxf(mx0, __shfl_xor_sync(0xffffffffu, mx0, 1));
        mx0 = fmaxf(mx0, __shfl_xor_sync(0xffffffffu, mx0, 2));
        mx1 = fmaxf(mx1, __shfl_xor_sync(0xffffffffu, mx1, 1));
        mx1 = fmaxf(mx1, __shfl_xor_sync(0xffffffffu, mx1, 2));
        float mn0 = fmaxf(m0, mx0), mn1 = fmaxf(m1, mx1);
        float a0 = __expf(m0 - mn0), a1 = __expf(m1 - mn1);
        m0 = mn0; m1 = mn1;
        float s0sum = 0.f, s1sum = 0.f;
#pragma unroll
        for (int nj = 0; nj < 16; nj++) {
            C[nj][0] = __expf(C[nj][0] - mn0); s0sum += C[nj][0];
            C[nj][1] = __expf(C[nj][1] - mn0); s0sum += C[nj][1];
            C[nj][2] = __expf(C[nj][2] - mn1); s1sum += C[nj][2];
            C[nj][3] = __expf(C[nj][3] - mn1); s1sum += C[nj][3];
        }
        s0sum += __shfl_xor_sync(0xffffffffu, s0sum, 1);
        s0sum += __shfl_xor_sync(0xffffffffu, s0sum, 2);
        s1sum += __shfl_xor_sync(0xffffffffu, s1sum, 1);
        s1sum += __shfl_xor_sync(0xffffffffu, s1sum, 2);
        l0 = l0 * a0 + s0sum;
        l1 = l1 * a1 + s1sum;
#pragma unroll
        for (int nj = 0; nj < 8; nj++) {
            O[nj][0] *= a0; O[nj][1] *= a0;
            O[nj][2] *= a1; O[nj][3] *= a1;
        }

        // ---- O += P V (fp16), P fragments repacked from C in registers ----
#pragma unroll
        for (int ki = 0; ki < 8; ki++) {
            uint32_t aP[4];
            aP[0] = f16pair(C[2*ki  ][0], C[2*ki  ][1]);
            aP[1] = f16pair(C[2*ki  ][2], C[2*ki  ][3]);
            aP[2] = f16pair(C[2*ki+1][0], C[2*ki+1][1]);
            aP[3] = f16pair(C[2*ki+1][2], C[2*ki+1][3]);
#pragma unroll
            for (int nj = 0; nj < 8; nj += 2) {
                uint32_t bv[4];
                int mm = lane >> 3;
                int row = ki*16 + (mm & 1)*8 + (lane & 7);
                int ch  = nj + (mm >> 1);
                uint32_t off = row*128 + ((ch ^ (row & 7)) << 4);
                ldsm_x4_t(bv, tV + off);
                mma_f16(O[nj],   aP, bv);
                mma_f16(O[nj+1], aP, bv + 2);
            }
        }
        __syncthreads();
    }

    // ---- epilogue: normalize, split to bf16 hi/lo, write [B,T,C] ----
    const float i0 = 1.f / l0, i1 = 1.f / l1;
    const int b = bh >> 4, hh = bh & 15;
#pragma unroll
    for (int nj = 0; nj < 8; nj++) {
        int col = hh*HDIM + nj*8 + 2*(lane & 3);
        size_t o0 = ((size_t)b*TQ + r0    ) * CD + col;
        size_t o1 = ((size_t)b*TQ + r0 + 8) * CD + col;
        uint32_t hi, lo;
        bf16split2(O[nj][0]*i0, O[nj][1]*i0, hi, lo);
        *(uint32_t*)(Yh + o0) = hi;
        *(uint32_t*)(Yl + o0) = lo;
        bf16split2(O[nj][2]*i1, O[nj][3]*i1, hi, lo);
        *(uint32_t*)(Yh + o1) = hi;
        *(uint32_t*)(Yl + o1) = lo;
    }
#undef AT_LOAD
}

// ---------------------------------------------------------------------------
extern "C" void kernel_launch(void* const* d_in, const int* in_sizes, int n_in,
                              void* d_out, int out_size)
{
    const float* x      = (const float*)d_in[0];
    const float* W_attn = (const float*)d_in[1];
    const float* b_attn = (const float*)d_in[2];
    const float* W_proj = (const float*)d_in[3];
    const float* b_proj = (const float*)d_in[4];
    float* out  = (float*)d_out;
    float* Kout = out + (size_t)YSZ;
    float* Vout = out + 2*(size_t)YSZ;

    __nv_bfloat16 *xh, *xl, *Yh, *Yl, *WaTh, *WaTl, *WpTh, *WpTl;
    __nv_bfloat16 *Qbh, *Qbl, *Kbh, *Kbl;
    __half *Vhf;
    cudaGetSymbolAddress((void**)&xh,   g_xh);
    cudaGetSymbolAddress((void**)&xl,   g_xl);
    cudaGetSymbolAddress((void**)&Yh,   g_Yh);
    cudaGetSymbolAddress((void**)&Yl,   g_Yl);
    cudaGetSymbolAddress((void**)&WaTh, g_WaTh);
    cudaGetSymbolAddress((void**)&WaTl, g_WaTl);
    cudaGetSymbolAddress((void**)&WpTh, g_WpTh);
    cudaGetSymbolAddress((void**)&WpTl, g_WpTl);
    cudaGetSymbolAddress((void**)&Qbh,  g_Qbh);
    cudaGetSymbolAddress((void**)&Qbl,  g_Qbl);
    cudaGetSymbolAddress((void**)&Kbh,  g_Kbh);
    cudaGetSymbolAddress((void**)&Kbl,  g_Kbl);
    cudaGetSymbolAddress((void**)&Vhf,  g_Vhf);

    static int attr_done = 0;
    if (!attr_done) {
        cudaFuncSetAttribute(attn3, cudaFuncAttributeMaxDynamicSharedMemorySize, (int)ATTN_SMEM);
        cudaFuncSetAttribute(mma_gemm, cudaFuncAttributeMaxDynamicSharedMemorySize, GEMM_SMEM);
        attr_done = 1;
    }

    // 1) split inputs to hi/lo bf16
    split_kernel<<<(MROWS*CD/4 + 255)/256, 256>>>(x, xh, xl, MROWS*CD/4);
    tsplit_kernel<<<dim3(3*CD/32, CD/32), 256>>>(W_attn, WaTh, WaTl, CD, 3*CD);
    tsplit_kernel<<<dim3(CD/32, CD/32), 256>>>(W_proj, WpTh, WpTl, CD, CD);

    // 2) qkv GEMM -> Q/K hi/lo bf16, V fp16, K/V fp32 outputs
    mma_gemm<<<dim3(3*CD/128, MROWS/128), 256, GEMM_SMEM>>>(
        xh, xl, WaTh, WaTl, b_attn, 0, nullptr, Kout, Vout);

    // 3) tensor-core causal flash attention -> Yh/Yl bf16
    attn3<<<dim3(TQ/64, BATCH*NHEAD), 128, ATTN_SMEM>>>(
        Qbh, Qbl, Kbh, Kbl, Vhf, Yh, Yl);

    // 4) proj GEMM -> y output
    mma_gemm<<<dim3(CD/128, MROWS/128), 256, GEMM_SMEM>>>(
        Yh, Yl, WpTh, WpTl, b_proj, 1, out, nullptr, nullptr);
}

// round 8
// speedup vs baseline: 8.7943x; 1.3218x over previous
#include <cuda_runtime.h>
#include <cuda_fp16.h>
#include <cstdint>

// Problem constants
#define TQ    2048
#define CD    1024
#define NHEAD 16
#define HDIM  64
#define BATCH 2
#define MROWS (BATCH*TQ)        // 4096
#define YSZ   (BATCH*TQ*CD)

// ---------------- mma.sync helpers (compute_80 baseline; HMMA on sm_103) ----
__device__ __forceinline__ uint32_t smem_u32(const void* p) {
    uint32_t a;
    asm("{ .reg .u64 t; cvta.to.shared.u64 t, %1; cvt.u32.u64 %0, t; }" : "=r"(a) : "l"(p));
    return a;
}
__device__ __forceinline__ void cp_async16(uint32_t saddr, const void* g) {
    asm volatile("cp.async.cg.shared.global [%0], [%1], 16;" :: "r"(saddr), "l"(g));
}
#define CP_COMMIT() asm volatile("cp.async.commit_group;" ::: "memory")
#define CP_WAIT0()  asm volatile("cp.async.wait_group 0;" ::: "memory")
#define CP_WAIT1()  asm volatile("cp.async.wait_group 1;" ::: "memory")

__device__ __forceinline__ void ldsm_x4(uint32_t* r, uint32_t addr) {
    asm volatile("ldmatrix.sync.aligned.m8n8.x4.shared.b16 {%0,%1,%2,%3}, [%4];"
        : "=r"(r[0]), "=r"(r[1]), "=r"(r[2]), "=r"(r[3]) : "r"(addr));
}
__device__ __forceinline__ void ldsm_x4_t(uint32_t* r, uint32_t addr) {
    asm volatile("ldmatrix.sync.aligned.m8n8.x4.trans.shared.b16 {%0,%1,%2,%3}, [%4];"
        : "=r"(r[0]), "=r"(r[1]), "=r"(r[2]), "=r"(r[3]) : "r"(addr));
}
__device__ __forceinline__ void mma_f16(float* c, const uint32_t* a, const uint32_t* b) {
    asm volatile("mma.sync.aligned.m16n8k16.row.col.f32.f16.f16.f32 "
        "{%0,%1,%2,%3}, {%4,%5,%6,%7}, {%8,%9}, {%0,%1,%2,%3};"
        : "+f"(c[0]), "+f"(c[1]), "+f"(c[2]), "+f"(c[3])
        : "r"(a[0]), "r"(a[1]), "r"(a[2]), "r"(a[3]), "r"(b[0]), "r"(b[1]));
}
// pack (lo, hi) floats -> f16x2 register (lo in low half)
__device__ __forceinline__ uint32_t f16pair(float lo, float hi) {
    uint32_t d;
    asm("cvt.rn.f16x2.f32 %0, %1, %2;" : "=r"(d) : "f"(hi), "f"(lo));
    return d;
}
// split (x,y) into fp16 hi/lo pairs packed as u32 (x in low half)
__device__ __forceinline__ void f16split2(float x, float y, uint32_t& hi, uint32_t& lo) {
    __half2 h = __floats2half2_rn(x, y);
    float hx = __half2float(__low2half(h));
    float hy = __half2float(__high2half(h));
    __half2 l = __floats2half2_rn(x - hx, y - hy);
    hi = *(uint32_t*)&h;
    lo = *(uint32_t*)&l;
}

// ---------------- global scratch (no allocation allowed) ----------------
__device__ __half g_Qfh[BATCH*NHEAD*TQ*HDIM], g_Qfl[BATCH*NHEAD*TQ*HDIM];
__device__ __half g_Kf [BATCH*NHEAD*TQ*HDIM];
__device__ __half g_Vf [BATCH*NHEAD*TQ*HDIM];
__device__ __half g_xh[MROWS*CD], g_xl[MROWS*CD];
__device__ __half g_Yh[MROWS*CD], g_Yl[MROWS*CD];
__device__ __half g_WaT[3*CD*CD];     // W_attn^T fp16 [3072,1024]
__device__ __half g_WpT[CD*CD];       // W_proj^T fp16 [1024,1024]

// ---------------- split / transpose kernels ----------------
__global__ __launch_bounds__(256) void split_kernel(
    const float* __restrict__ src, __half* __restrict__ hi,
    __half* __restrict__ lo, int n4)
{
    int i = blockIdx.x * 256 + threadIdx.x;
    if (i >= n4) return;
    float4 v = ((const float4*)src)[i];
    float vv[4] = {v.x, v.y, v.z, v.w};
    __half h[4], l[4];
#pragma unroll
    for (int j = 0; j < 4; j++) {
        h[j] = __float2half(vv[j]);
        l[j] = __float2half(vv[j] - __half2float(h[j]));
    }
    ((uint2*)hi)[i] = *(uint2*)h;
    ((uint2*)lo)[i] = *(uint2*)l;
}

// transpose: W [K,N] fp32 -> T fp16 [N,K]
__global__ __launch_bounds__(256) void tsplit_kernel(
    const float* __restrict__ W, __half* __restrict__ Th, int K, int N)
{
    __shared__ float tile[32][33];
    int bx = blockIdx.x * 32, by = blockIdx.y * 32;
    int tx = threadIdx.x & 31, ty = threadIdx.x >> 5;
#pragma unroll
    for (int r = ty; r < 32; r += 8)
        tile[r][tx] = W[(size_t)(by + r) * N + bx + tx];
    __syncthreads();
#pragma unroll
    for (int r = ty; r < 32; r += 8)
        Th[(size_t)(bx + r) * K + by + tx] = __float2half(tile[tx][r]);
}

// ---------------- mma.sync 2-term fp16 GEMM ----------------
// C = (Ah + Al) @ Bh^T + bias;  CTA 128x128, 8 warps (32x64 warp tiles),
// K-chunk 64, 3 stages, one __syncthreads per chunk.
#define TILE_SZ   16384
#define STAGE_SZ  (3*TILE_SZ)      // Ah | Al | Bh = 48KB
#define GEMM_SMEM (3*STAGE_SZ)     // 144KB

__global__ __launch_bounds__(256) void mma_gemm(
    const __half* __restrict__ Ah, const __half* __restrict__ Al,
    const __half* __restrict__ Bh,
    const float* __restrict__ bias, int mode,
    float* __restrict__ out, float* __restrict__ Kout, float* __restrict__ Vout)
{
    extern __shared__ __align__(1024) char sm[];
    const uint32_t sb = smem_u32(sm);
    const int tid = threadIdx.x, lane = tid & 31, wid = tid >> 5;
    const int wm = wid & 3, wn = wid >> 2;
    const int m0 = blockIdx.y * 128, n0 = blockIdx.x * 128;

    int lr[4], lsw[4];
#pragma unroll
    for (int p = 0; p < 4; p++) {
        int i = tid + p * 256;
        int r = i >> 3, c = i & 7;
        lr[p] = r;
        lsw[p] = r * 128 + ((c ^ (r & 7)) << 4);
    }

#define LOAD_CHUNK(kc, stage) do {                                          \
        uint32_t s0 = sb + (stage) * STAGE_SZ;                              \
        int kcol = (kc) * 64;                                               \
        _Pragma("unroll")                                                   \
        for (int p = 0; p < 4; p++) {                                       \
            int c8 = ((tid + p*256) & 7) * 8;                               \
            size_t ga = (size_t)(m0 + lr[p]) * CD + kcol + c8;              \
            size_t gb = (size_t)(n0 + lr[p]) * CD + kcol + c8;              \
            cp_async16(s0 + 0*TILE_SZ + lsw[p], Ah + ga);                   \
            cp_async16(s0 + 1*TILE_SZ + lsw[p], Al + ga);                   \
            cp_async16(s0 + 2*TILE_SZ + lsw[p], Bh + gb);                   \
        }                                                                   \
    } while (0)

    float C[2][8][4];
#pragma unroll
    for (int mi = 0; mi < 2; mi++)
#pragma unroll
        for (int ni = 0; ni < 8; ni++)
#pragma unroll
            for (int q = 0; q < 4; q++) C[mi][ni][q] = 0.f;

    const int ar  = wm*32 + (lane & 15);
    const int ach = (lane >> 4);
    // B x4 ldsm: lane-group m = lane>>3 -> (nj offset m>>1, k-chunk m&1)
    const int brr = wn*64 + ((lane >> 4) & 1)*8 + (lane & 7);
    const int bcc = (lane >> 3) & 1;

    LOAD_CHUNK(0, 0); CP_COMMIT();
    LOAD_CHUNK(1, 1); CP_COMMIT();

    for (int kc = 0; kc < 16; kc++) {
        if (kc == 15) { CP_WAIT0(); } else { CP_WAIT1(); }
        __syncthreads();
        if (kc + 2 < 16) { LOAD_CHUNK(kc + 2, (kc + 2) % 3); CP_COMMIT(); }

        const uint32_t s0 = sb + (kc % 3) * STAGE_SZ;
        const uint32_t tAh = s0, tAl = s0 + TILE_SZ, tBh = s0 + 2*TILE_SZ;

#pragma unroll
        for (int ks = 0; ks < 4; ks++) {
            uint32_t aH[2][4], aL[2][4];
#pragma unroll
            for (int mi = 0; mi < 2; mi++) {
                int r = ar + mi*16;
                int c = ks*2 + ach;
                uint32_t off = r*128 + ((c ^ (r & 7)) << 4);
                ldsm_x4(aH[mi], tAh + off);
                ldsm_x4(aL[mi], tAl + off);
            }
#pragma unroll
            for (int ni = 0; ni < 8; ni += 2) {
                uint32_t bv[4];
                int row = brr + ni*8;
                int c = ks*2 + bcc;
                uint32_t off = row*128 + ((c ^ (row & 7)) << 4);
                ldsm_x4(bv, tBh + off);
                mma_f16(C[0][ni],   aH[0], bv);
                mma_f16(C[1][ni],   aH[1], bv);
                mma_f16(C[0][ni+1], aH[0], bv + 2);
                mma_f16(C[1][ni+1], aH[1], bv + 2);
                mma_f16(C[0][ni],   aL[0], bv);
                mma_f16(C[1][ni],   aL[1], bv);
                mma_f16(C[0][ni+1], aL[0], bv + 2);
                mma_f16(C[1][ni+1], aL[1], bv + 2);
            }
        }
    }

    // Epilogue
    const int mbase = m0 + wm*32 + (lane >> 2);
    const int npair = 2*(lane & 3);
#pragma unroll
    for (int mi = 0; mi < 2; mi++) {
#pragma unroll
        for (int half = 0; half < 2; half++) {
            int m = mbase + mi*16 + half*8;
            int b = m >> 11, tt = m & (TQ - 1);
#pragma unroll
            for (int ni = 0; ni < 8; ni++) {
                int n = n0 + wn*64 + ni*8 + npair;
                float2 bvs = *(const float2*)(bias + n);
                float2 v;
                v.x = C[mi][ni][half*2+0] + bvs.x;
                v.y = C[mi][ni][half*2+1] + bvs.y;
                if (mode == 0) {
                    int sec = n >> 10, within = n & 1023;
                    int h = within >> 6, dd = within & 63;
                    size_t idx = ((size_t)(b*NHEAD + h)*TQ + tt)*HDIM + dd;
                    if (sec == 0) {
                        uint32_t hi, lo;
                        f16split2(v.x * 0.125f, v.y * 0.125f, hi, lo);
                        *(uint32_t*)(g_Qfh + idx) = hi;
                        *(uint32_t*)(g_Qfl + idx) = lo;
                    } else if (sec == 1) {
                        *(float2*)(Kout + idx) = v;
                        __half2 hv = __floats2half2_rn(v.x, v.y);
                        *(__half2*)(g_Kf + idx) = hv;
                    } else {
                        *(float2*)(Vout + idx) = v;
                        __half2 hv = __floats2half2_rn(v.x, v.y);
                        *(__half2*)(g_Vf + idx) = hv;
                    }
                } else {
                    *(float2*)(out + (size_t)m*CD + n) = v;
                }
            }
        }
    }
#undef LOAD_CHUNK
}

// ---------------------------------------------------------------------------
// Tensor-core flash attention: CTA = 64 q-rows (4 warps), key blocks of 128.
// S = (Qh+Ql) K^T fp16 (2-term, K single fp16); PV fp16 single-term.
// ---------------------------------------------------------------------------
#define AT_STAGE 32768                 // Kf(16K) | V(16K)
#define ATTN_SMEM (2*AT_STAGE)         // 64KB -> 3 CTAs/SM

__global__ __launch_bounds__(128) void attn3(
    const __half* __restrict__ Qh, const __half* __restrict__ Ql,
    const __half* __restrict__ Kf, const __half* __restrict__ Vf,
    __half* __restrict__ Yh, __half* __restrict__ Yl)
{
    extern __shared__ __align__(1024) char sm[];
    const uint32_t sb = smem_u32(sm);
    const int tid = threadIdx.x, lane = tid & 31, w = tid >> 5;
    const int bh = blockIdx.y;
    const int qt = gridDim.x - 1 - blockIdx.x;   // big tiles first
    const int q0 = qt * 64;
    const int nkb = (q0 + 191) >> 7;
    const size_t qbase = (size_t)bh * TQ;

    // Resident Q A-fragments (hi/lo)
    const int r0 = q0 + w*16 + (lane >> 2);
    uint32_t aQh[4][4], aQl[4][4];
#pragma unroll
    for (int ks = 0; ks < 4; ks++) {
        int k = ks*16 + 2*(lane & 3);
        aQh[ks][0] = *(const uint32_t*)(Qh + (qbase + r0    )*HDIM + k);
        aQh[ks][1] = *(const uint32_t*)(Qh + (qbase + r0 + 8)*HDIM + k);
        aQh[ks][2] = *(const uint32_t*)(Qh + (qbase + r0    )*HDIM + k + 8);
        aQh[ks][3] = *(const uint32_t*)(Qh + (qbase + r0 + 8)*HDIM + k + 8);
        aQl[ks][0] = *(const uint32_t*)(Ql + (qbase + r0    )*HDIM + k);
        aQl[ks][1] = *(const uint32_t*)(Ql + (qbase + r0 + 8)*HDIM + k);
        aQl[ks][2] = *(const uint32_t*)(Ql + (qbase + r0    )*HDIM + k + 8);
        aQl[ks][3] = *(const uint32_t*)(Ql + (qbase + r0 + 8)*HDIM + k + 8);
    }

#define AT_LOAD(kb, s) do {                                                  \
        uint32_t s0 = sb + (s) * AT_STAGE;                                   \
        int k0 = (kb) * 128;                                                 \
        _Pragma("unroll")                                                    \
        for (int p = 0; p < 8; p++) {                                        \
            int i = tid + p * 128;                                           \
            int r = i >> 3, c = i & 7;                                       \
            uint32_t sw = r*128 + ((c ^ (r & 7)) << 4);                      \
            size_t g = (qbase + k0 + r) * HDIM + c*8;                        \
            cp_async16(s0 +         sw, Kf + g);                             \
            cp_async16(s0 + 16384 + sw, Vf + g);                             \
        }                                                                    \
    } while (0)

    float m0 = -1e30f, m1 = -1e30f, l0 = 0.f, l1 = 0.f;
    float O[8][4];
#pragma unroll
    for (int nj = 0; nj < 8; nj++)
#pragma unroll
        for (int q = 0; q < 4; q++) O[nj][q] = 0.f;

    AT_LOAD(0, 0); CP_COMMIT();

    for (int kb = 0; kb < nkb; kb++) {
        const bool more = (kb + 1 < nkb);
        if (more) { AT_LOAD(kb + 1, (kb + 1) & 1); CP_COMMIT(); }
        if (more) { CP_WAIT1(); } else { CP_WAIT0(); }
        __syncthreads();
        const uint32_t s0 = sb + (kb & 1) * AT_STAGE;
        const uint32_t tKF = s0, tV = s0 + 16384;

        // ---- S = Q K^T (2-term fp16), 16 n-tiles of 8 keys ----
        float C[16][4];
#pragma unroll
        for (int nj = 0; nj < 16; nj++)
#pragma unroll
            for (int q = 0; q < 4; q++) C[nj][q] = 0.f;

#pragma unroll
        for (int ks = 0; ks < 4; ks++) {
#pragma unroll
            for (int nj = 0; nj < 16; nj += 2) {
                uint32_t bk[4];
                int mm = lane >> 3;
                int row = nj*8 + (mm >> 1)*8 + (lane & 7);
                int ch  = 2*ks + (mm & 1);
                uint32_t off = row*128 + ((ch ^ (row & 7)) << 4);
                ldsm_x4(bk, tKF + off);
                mma_f16(C[nj],   aQh[ks], bk);
                mma_f16(C[nj+1], aQh[ks], bk + 2);
                mma_f16(C[nj],   aQl[ks], bk);
                mma_f16(C[nj+1], aQl[ks], bk + 2);
            }
        }

        // ---- causal mask (last block only) ----
        if (kb == nkb - 1) {
#pragma unroll
            for (int nj = 0; nj < 16; nj++) {
                int col = kb*128 + nj*8 + 2*(lane & 3);
                if (col     > r0    ) C[nj][0] = -1e30f;
                if (col + 1 > r0    ) C[nj][1] = -1e30f;
                if (col     > r0 + 8) C[nj][2] = -1e30f;
                if (col + 1 > r0 + 8) C[nj][3] = -1e30f;
            }
        }

        // ---- online softmax ----
        float mx0 = -1e30f, mx1 = -1e30f;
#pragma unroll
        for (int nj = 0; nj < 16; nj++) {
            mx0 = fmaxf(mx0, fmaxf(C[nj][0], C[nj][1]));
            mx1 = fmaxf(mx1, fmaxf(C[nj][2], C[nj][3]));
        }
        mx0 = fmaxf(mx0, __shfl_xor_sync(0xffffffffu, mx0, 1));
        mx0 = fmaxf(mx0, __shfl_xor_sync(0xffffffffu, mx0, 2));
        mx1 = fmaxf(mx1, __shfl_xor_sync(0xffffffffu, mx1, 1));
        mx1 = fmaxf(mx1, __shfl_xor_sync(0xffffffffu, mx1, 2));
        float mn0 = fmaxf(m0, mx0), mn1 = fmaxf(m1, mx1);
        float a0 = __expf(m0 - mn0), a1 = __expf(m1 - mn1);
        m0 = mn0; m1 = mn1;
        float s0sum = 0.f, s1sum = 0.f;
#pragma unroll
        for (int nj = 0; nj < 16; nj++) {
            C[nj][0] = __expf(C[nj][0] - mn0); s0sum += C[nj][0];
            C[nj][1] = __expf(C[nj][1] - mn0); s0sum += C[nj][1];
            C[nj][2] = __expf(C[nj][2] - mn1); s1sum += C[nj][2];
            C[nj][3] = __expf(C[nj][3] - mn1); s1sum += C[nj][3];
        }
        s0sum += __shfl_xor_sync(0xffffffffu, s0sum, 1);
        s0sum += __shfl_xor_sync(0xffffffffu, s0sum, 2);
        s1sum += __shfl_xor_sync(0xffffffffu, s1sum, 1);
        s1sum += __shfl_xor_sync(0xffffffffu, s1sum, 2);
        l0 = l0 * a0 + s0sum;
        l1 = l1 * a1 + s1sum;
#pragma unroll
        for (int nj = 0; nj < 8; nj++) {
            O[nj][0] *= a0; O[nj][1] *= a0;
            O[nj][2] *= a1; O[nj][3] *= a1;
        }

        // ---- O += P V (fp16), P repacked from C in registers ----
#pragma unroll
        for (int ki = 0; ki < 8; ki++) {
            uint32_t aP[4];
            aP[0] = f16pair(C[2*ki  ][0], C[2*ki  ][1]);
            aP[1] = f16pair(C[2*ki  ][2], C[2*ki  ][3]);
            aP[2] = f16pair(C[2*ki+1][0], C[2*ki+1][1]);
            aP[3] = f16pair(C[2*ki+1][2], C[2*ki+1][3]);
#pragma unroll
            for (int nj = 0; nj < 8; nj += 2) {
                uint32_t bv[4];
                int mm = lane >> 3;
                int row = ki*16 + (mm & 1)*8 + (lane & 7);
                int ch  = nj + (mm >> 1);
                uint32_t off = row*128 + ((ch ^ (row & 7)) << 4);
                ldsm_x4_t(bv, tV + off);
                mma_f16(O[nj],   aP, bv);
                mma_f16(O[nj+1], aP, bv + 2);
            }
        }
        __syncthreads();
    }

    // ---- epilogue: normalize, split fp16 hi/lo, write [B,T,C] ----
    const float i0 = 1.f / l0, i1 = 1.f / l1;
    const int b = bh >> 4, hh = bh & 15;
#pragma unroll
    for (int nj = 0; nj < 8; nj++) {
        int col = hh*HDIM + nj*8 + 2*(lane & 3);
        size_t o0 = ((size_t)b*TQ + r0    ) * CD + col;
        size_t o1 = ((size_t)b*TQ + r0 + 8) * CD + col;
        uint32_t hi, lo;
        f16split2(O[nj][0]*i0, O[nj][1]*i0, hi, lo);
        *(uint32_t*)(Yh + o0) = hi;
        *(uint32_t*)(Yl + o0) = lo;
        f16split2(O[nj][2]*i1, O[nj][3]*i1, hi, lo);
        *(uint32_t*)(Yh + o1) = hi;
        *(uint32_t*)(Yl + o1) = lo;
    }
#undef AT_LOAD
}

// ---------------------------------------------------------------------------
extern "C" void kernel_launch(void* const* d_in, const int* in_sizes, int n_in,
                              void* d_out, int out_size)
{
    const float* x      = (const float*)d_in[0];
    const float* W_attn = (const float*)d_in[1];
    const float* b_attn = (const float*)d_in[2];
    const float* W_proj = (const float*)d_in[3];
    const float* b_proj = (const float*)d_in[4];
    float* out  = (float*)d_out;
    float* Kout = out + (size_t)YSZ;
    float* Vout = out + 2*(size_t)YSZ;

    __half *xh, *xl, *Yh, *Yl, *WaT, *WpT, *Qfh, *Qfl, *Kf, *Vf;
    cudaGetSymbolAddress((void**)&xh,  g_xh);
    cudaGetSymbolAddress((void**)&xl,  g_xl);
    cudaGetSymbolAddress((void**)&Yh,  g_Yh);
    cudaGetSymbolAddress((void**)&Yl,  g_Yl);
    cudaGetSymbolAddress((void**)&WaT, g_WaT);
    cudaGetSymbolAddress((void**)&WpT, g_WpT);
    cudaGetSymbolAddress((void**)&Qfh, g_Qfh);
    cudaGetSymbolAddress((void**)&Qfl, g_Qfl);
    cudaGetSymbolAddress((void**)&Kf,  g_Kf);
    cudaGetSymbolAddress((void**)&Vf,  g_Vf);

    static int attr_done = 0;
    if (!attr_done) {
        cudaFuncSetAttribute(attn3, cudaFuncAttributeMaxDynamicSharedMemorySize, (int)ATTN_SMEM);
        cudaFuncSetAttribute(mma_gemm, cudaFuncAttributeMaxDynamicSharedMemorySize, GEMM_SMEM);
        attr_done = 1;
    }

    // 1) precision prep
    split_kernel<<<(MROWS*CD/4 + 255)/256, 256>>>(x, xh, xl, MROWS*CD/4);
    tsplit_kernel<<<dim3(3*CD/32, CD/32), 256>>>(W_attn, WaT, CD, 3*CD);
    tsplit_kernel<<<dim3(CD/32, CD/32), 256>>>(W_proj, WpT, CD, CD);

    // 2) qkv GEMM (2-term fp16) -> Q hi/lo, K/V fp16 + fp32 outputs
    mma_gemm<<<dim3(3*CD/128, MROWS/128), 256, GEMM_SMEM>>>(
        xh, xl, WaT, b_attn, 0, nullptr, Kout, Vout);

    // 3) tensor-core causal flash attention -> Yh/Yl fp16
    attn3<<<dim3(TQ/64, BATCH*NHEAD), 128, ATTN_SMEM>>>(
        Qfh, Qfl, Kf, Vf, Yh, Yl);

    // 4) proj GEMM (2-term fp16) -> y
    mma_gemm<<<dim3(CD/128, MROWS/128), 256, GEMM_SMEM>>>(
        Yh, Yl, WpT, b_proj, 1, out, nullptr, nullptr);
}

// round 9
// speedup vs baseline: 9.6267x; 1.0947x over previous
#include <cuda_runtime.h>
#include <cuda_fp16.h>
#include <cstdint>

// Problem constants
#define TQ    2048
#define CD    1024
#define NHEAD 16
#define HDIM  64
#define BATCH 2
#define MROWS (BATCH*TQ)        // 4096
#define YSZ   (BATCH*TQ*CD)

// ---------------- mma.sync helpers (compute_80 baseline; HMMA on sm_103) ----
__device__ __forceinline__ uint32_t smem_u32(const void* p) {
    uint32_t a;
    asm("{ .reg .u64 t; cvta.to.shared.u64 t, %1; cvt.u32.u64 %0, t; }" : "=r"(a) : "l"(p));
    return a;
}
__device__ __forceinline__ void cp_async16(uint32_t saddr, const void* g) {
    asm volatile("cp.async.cg.shared.global [%0], [%1], 16;" :: "r"(saddr), "l"(g));
}
#define CP_COMMIT() asm volatile("cp.async.commit_group;" ::: "memory")
#define CP_WAIT0()  asm volatile("cp.async.wait_group 0;" ::: "memory")
#define CP_WAIT1()  asm volatile("cp.async.wait_group 1;" ::: "memory")

__device__ __forceinline__ void ldsm_x4(uint32_t* r, uint32_t addr) {
    asm volatile("ldmatrix.sync.aligned.m8n8.x4.shared.b16 {%0,%1,%2,%3}, [%4];"
        : "=r"(r[0]), "=r"(r[1]), "=r"(r[2]), "=r"(r[3]) : "r"(addr));
}
__device__ __forceinline__ void ldsm_x4_t(uint32_t* r, uint32_t addr) {
    asm volatile("ldmatrix.sync.aligned.m8n8.x4.trans.shared.b16 {%0,%1,%2,%3}, [%4];"
        : "=r"(r[0]), "=r"(r[1]), "=r"(r[2]), "=r"(r[3]) : "r"(addr));
}
__device__ __forceinline__ void mma_f16(float* c, const uint32_t* a, const uint32_t* b) {
    asm volatile("mma.sync.aligned.m16n8k16.row.col.f32.f16.f16.f32 "
        "{%0,%1,%2,%3}, {%4,%5,%6,%7}, {%8,%9}, {%0,%1,%2,%3};"
        : "+f"(c[0]), "+f"(c[1]), "+f"(c[2]), "+f"(c[3])
        : "r"(a[0]), "r"(a[1]), "r"(a[2]), "r"(a[3]), "r"(b[0]), "r"(b[1]));
}
// pack (lo, hi) floats -> f16x2 register (lo in low half)
__device__ __forceinline__ uint32_t f16pair(float lo, float hi) {
    uint32_t d;
    asm("cvt.rn.f16x2.f32 %0, %1, %2;" : "=r"(d) : "f"(hi), "f"(lo));
    return d;
}
// split (x,y) into fp16 hi/lo pairs packed as u32 (x in low half)
__device__ __forceinline__ void f16split2(float x, float y, uint32_t& hi, uint32_t& lo) {
    __half2 h = __floats2half2_rn(x, y);
    float hx = __half2float(__low2half(h));
    float hy = __half2float(__high2half(h));
    __half2 l = __floats2half2_rn(x - hx, y - hy);
    hi = *(uint32_t*)&h;
    lo = *(uint32_t*)&l;
}

// ---------------- global scratch (no allocation allowed) ----------------
__device__ __half g_Qfh[BATCH*NHEAD*TQ*HDIM], g_Qfl[BATCH*NHEAD*TQ*HDIM];
__device__ __half g_Kf [BATCH*NHEAD*TQ*HDIM];
__device__ __half g_Vf [BATCH*NHEAD*TQ*HDIM];
__device__ __half g_xh[MROWS*CD], g_xl[MROWS*CD];
__device__ __half g_Yh[MROWS*CD], g_Yl[MROWS*CD];
__device__ __half g_WaT[3*CD*CD];     // W_attn^T fp16 [3072,1024]
__device__ __half g_WpT[CD*CD];       // W_proj^T fp16 [1024,1024]

// ---------------- split / transpose kernels ----------------
__global__ __launch_bounds__(256) void split_kernel(
    const float* __restrict__ src, __half* __restrict__ hi,
    __half* __restrict__ lo, int n4)
{
    int i = blockIdx.x * 256 + threadIdx.x;
    if (i >= n4) return;
    float4 v = ((const float4*)src)[i];
    float vv[4] = {v.x, v.y, v.z, v.w};
    __half h[4], l[4];
#pragma unroll
    for (int j = 0; j < 4; j++) {
        h[j] = __float2half(vv[j]);
        l[j] = __float2half(vv[j] - __half2float(h[j]));
    }
    ((uint2*)hi)[i] = *(uint2*)h;
    ((uint2*)lo)[i] = *(uint2*)l;
}

// transpose: W [K,N] fp32 -> T fp16 [N,K]
__global__ __launch_bounds__(256) void tsplit_kernel(
    const float* __restrict__ W, __half* __restrict__ Th, int K, int N)
{
    __shared__ float tile[32][33];
    int bx = blockIdx.x * 32, by = blockIdx.y * 32;
    int tx = threadIdx.x & 31, ty = threadIdx.x >> 5;
#pragma unroll
    for (int r = ty; r < 32; r += 8)
        tile[r][tx] = W[(size_t)(by + r) * N + bx + tx];
    __syncthreads();
#pragma unroll
    for (int r = ty; r < 32; r += 8)
        Th[(size_t)(bx + r) * K + by + tx] = __float2half(tile[tx][r]);
}

// ---------------- mma.sync 2-term fp16 GEMM ----------------
// C = (Ah + Al) @ Bh^T + bias;  CTA 128x128, 8 warps (32x64 warp tiles),
// K-chunk 64, 2 stages (96KB) -> 2 CTAs/SM for cross-CTA latency hiding.
#define TILE_SZ   16384
#define STAGE_SZ  (3*TILE_SZ)      // Ah | Al | Bh = 48KB
#define GEMM_SMEM (2*STAGE_SZ)     // 96KB

__global__ __launch_bounds__(256, 2) void mma_gemm(
    const __half* __restrict__ Ah, const __half* __restrict__ Al,
    const __half* __restrict__ Bh,
    const float* __restrict__ bias, int mode,
    float* __restrict__ out, float* __restrict__ Kout, float* __restrict__ Vout)
{
    extern __shared__ __align__(1024) char sm[];
    const uint32_t sb = smem_u32(sm);
    const int tid = threadIdx.x, lane = tid & 31, wid = tid >> 5;
    const int wm = wid & 3, wn = wid >> 2;
    const int m0 = blockIdx.y * 128, n0 = blockIdx.x * 128;

    int lr[4], lsw[4];
#pragma unroll
    for (int p = 0; p < 4; p++) {
        int i = tid + p * 256;
        int r = i >> 3, c = i & 7;
        lr[p] = r;
        lsw[p] = r * 128 + ((c ^ (r & 7)) << 4);
    }

#define LOAD_CHUNK(kc, stage) do {                                          \
        uint32_t s0 = sb + (stage) * STAGE_SZ;                              \
        int kcol = (kc) * 64;                                               \
        _Pragma("unroll")                                                   \
        for (int p = 0; p < 4; p++) {                                       \
            int c8 = ((tid + p*256) & 7) * 8;                               \
            size_t ga = (size_t)(m0 + lr[p]) * CD + kcol + c8;              \
            size_t gb = (size_t)(n0 + lr[p]) * CD + kcol + c8;              \
            cp_async16(s0 + 0*TILE_SZ + lsw[p], Ah + ga);                   \
            cp_async16(s0 + 1*TILE_SZ + lsw[p], Al + ga);                   \
            cp_async16(s0 + 2*TILE_SZ + lsw[p], Bh + gb);                   \
        }                                                                   \
    } while (0)

    float C[2][8][4];
#pragma unroll
    for (int mi = 0; mi < 2; mi++)
#pragma unroll
        for (int ni = 0; ni < 8; ni++)
#pragma unroll
            for (int q = 0; q < 4; q++) C[mi][ni][q] = 0.f;

    const int ar  = wm*32 + (lane & 15);
    const int ach = (lane >> 4);
    const int brr = wn*64 + ((lane >> 4) & 1)*8 + (lane & 7);
    const int bcc = (lane >> 3) & 1;

    LOAD_CHUNK(0, 0); CP_COMMIT();
    LOAD_CHUNK(1, 1); CP_COMMIT();

    for (int kc = 0; kc < 16; kc++) {
        if (kc == 15) { CP_WAIT0(); } else { CP_WAIT1(); }
        __syncthreads();

        const uint32_t s0 = sb + (kc & 1) * STAGE_SZ;
        const uint32_t tAh = s0, tAl = s0 + TILE_SZ, tBh = s0 + 2*TILE_SZ;

#pragma unroll
        for (int ks = 0; ks < 4; ks++) {
            uint32_t aH[2][4], aL[2][4];
#pragma unroll
            for (int mi = 0; mi < 2; mi++) {
                int r = ar + mi*16;
                int c = ks*2 + ach;
                uint32_t off = r*128 + ((c ^ (r & 7)) << 4);
                ldsm_x4(aH[mi], tAh + off);
                ldsm_x4(aL[mi], tAl + off);
            }
#pragma unroll
            for (int ni = 0; ni < 8; ni += 2) {
                uint32_t bv[4];
                int row = brr + ni*8;
                int c = ks*2 + bcc;
                uint32_t off = row*128 + ((c ^ (row & 7)) << 4);
                ldsm_x4(bv, tBh + off);
                mma_f16(C[0][ni],   aH[0], bv);
                mma_f16(C[1][ni],   aH[1], bv);
                mma_f16(C[0][ni+1], aH[0], bv + 2);
                mma_f16(C[1][ni+1], aH[1], bv + 2);
                mma_f16(C[0][ni],   aL[0], bv);
                mma_f16(C[1][ni],   aL[1], bv);
                mma_f16(C[0][ni+1], aL[0], bv + 2);
                mma_f16(C[1][ni+1], aL[1], bv + 2);
            }
        }
        __syncthreads();
        if (kc + 2 < 16) { LOAD_CHUNK(kc + 2, kc & 1); CP_COMMIT(); }
    }

    // Epilogue
    const int mbase = m0 + wm*32 + (lane >> 2);
    const int npair = 2*(lane & 3);
#pragma unroll
    for (int mi = 0; mi < 2; mi++) {
#pragma unroll
        for (int half = 0; half < 2; half++) {
            int m = mbase + mi*16 + half*8;
            int b = m >> 11, tt = m & (TQ - 1);
#pragma unroll
            for (int ni = 0; ni < 8; ni++) {
                int n = n0 + wn*64 + ni*8 + npair;
                float2 bvs = *(const float2*)(bias + n);
                float2 v;
                v.x = C[mi][ni][half*2+0] + bvs.x;
                v.y = C[mi][ni][half*2+1] + bvs.y;
                if (mode == 0) {
                    int sec = n >> 10, within = n & 1023;
                    int h = within >> 6, dd = within & 63;
                    size_t idx = ((size_t)(b*NHEAD + h)*TQ + tt)*HDIM + dd;
                    if (sec == 0) {
                        uint32_t hi, lo;
                        f16split2(v.x * 0.125f, v.y * 0.125f, hi, lo);
                        *(uint32_t*)(g_Qfh + idx) = hi;
                        *(uint32_t*)(g_Qfl + idx) = lo;
                    } else if (sec == 1) {
                        *(float2*)(Kout + idx) = v;
                        __half2 hv = __floats2half2_rn(v.x, v.y);
                        *(__half2*)(g_Kf + idx) = hv;
                    } else {
                        *(float2*)(Vout + idx) = v;
                        __half2 hv = __floats2half2_rn(v.x, v.y);
                        *(__half2*)(g_Vf + idx) = hv;
                    }
                } else {
                    *(float2*)(out + (size_t)m*CD + n) = v;
                }
            }
        }
    }
#undef LOAD_CHUNK
}

// ---------------------------------------------------------------------------
// Tensor-core flash attention: CTA = 64 q-rows (4 warps), key blocks of 128.
// S = (Qh+Ql) K^T fp16 (2-term, K single fp16); PV fp16 single-term.
// ---------------------------------------------------------------------------
#define AT_STAGE 32768                 // Kf(16K) | V(16K)
#define ATTN_SMEM (2*AT_STAGE)         // 64KB -> 3 CTAs/SM

__global__ __launch_bounds__(128) void attn3(
    const __half* __restrict__ Qh, const __half* __restrict__ Ql,
    const __half* __restrict__ Kf, const __half* __restrict__ Vf,
    __half* __restrict__ Yh, __half* __restrict__ Yl)
{
    extern __shared__ __align__(1024) char sm[];
    const uint32_t sb = smem_u32(sm);
    const int tid = threadIdx.x, lane = tid & 31, w = tid >> 5;
    const int bh = blockIdx.y;
    const int qt = gridDim.x - 1 - blockIdx.x;   // big tiles first
    const int q0 = qt * 64;
    const int nkb = (q0 + 191) >> 7;
    const size_t qbase = (size_t)bh * TQ;

    // Resident Q A-fragments (hi/lo)
    const int r0 = q0 + w*16 + (lane >> 2);
    uint32_t aQh[4][4], aQl[4][4];
#pragma unroll
    for (int ks = 0; ks < 4; ks++) {
        int k = ks*16 + 2*(lane & 3);
        aQh[ks][0] = *(const uint32_t*)(Qh + (qbase + r0    )*HDIM + k);
        aQh[ks][1] = *(const uint32_t*)(Qh + (qbase + r0 + 8)*HDIM + k);
        aQh[ks][2] = *(const uint32_t*)(Qh + (qbase + r0    )*HDIM + k + 8);
        aQh[ks][3] = *(const uint32_t*)(Qh + (qbase + r0 + 8)*HDIM + k + 8);
        aQl[ks][0] = *(const uint32_t*)(Ql + (qbase + r0    )*HDIM + k);
        aQl[ks][1] = *(const uint32_t*)(Ql + (qbase + r0 + 8)*HDIM + k);
        aQl[ks][2] = *(const uint32_t*)(Ql + (qbase + r0    )*HDIM + k + 8);
        aQl[ks][3] = *(const uint32_t*)(Ql + (qbase + r0 + 8)*HDIM + k + 8);
    }

#define AT_LOAD(kb, s) do {                                                  \
        uint32_t s0 = sb + (s) * AT_STAGE;                                   \
        int k0 = (kb) * 128;                                                 \
        _Pragma("unroll")                                                    \
        for (int p = 0; p < 8; p++) {                                        \
            int i = tid + p * 128;                                           \
            int r = i >> 3, c = i & 7;                                       \
            uint32_t sw = r*128 + ((c ^ (r & 7)) << 4);                      \
            size_t g = (qbase + k0 + r) * HDIM + c*8;                        \
            cp_async16(s0 +         sw, Kf + g);                             \
            cp_async16(s0 + 16384 + sw, Vf + g);                             \
        }                                                                    \
    } while (0)

    float m0 = -1e30f, m1 = -1e30f, l0 = 0.f, l1 = 0.f;
    float O[8][4];
#pragma unroll
    for (int nj = 0; nj < 8; nj++)
#pragma unroll
        for (int q = 0; q < 4; q++) O[nj][q] = 0.f;

    AT_LOAD(0, 0); CP_COMMIT();

    for (int kb = 0; kb < nkb; kb++) {
        const bool more = (kb + 1 < nkb);
        if (more) { AT_LOAD(kb + 1, (kb + 1) & 1); CP_COMMIT(); }
        if (more) { CP_WAIT1(); } else { CP_WAIT0(); }
        __syncthreads();
        const uint32_t s0 = sb + (kb & 1) * AT_STAGE;
        const uint32_t tKF = s0, tV = s0 + 16384;

        // ---- S = Q K^T (2-term fp16), 16 n-tiles of 8 keys ----
        float C[16][4];
#pragma unroll
        for (int nj = 0; nj < 16; nj++)
#pragma unroll
            for (int q = 0; q < 4; q++) C[nj][q] = 0.f;

#pragma unroll
        for (int ks = 0; ks < 4; ks++) {
#pragma unroll
            for (int nj = 0; nj < 16; nj += 2) {
                uint32_t bk[4];
                int mm = lane >> 3;
                int row = nj*8 + (mm >> 1)*8 + (lane & 7);
                int ch  = 2*ks + (mm & 1);
                uint32_t off = row*128 + ((ch ^ (row & 7)) << 4);
                ldsm_x4(bk, tKF + off);
                mma_f16(C[nj],   aQh[ks], bk);
                mma_f16(C[nj+1], aQh[ks], bk + 2);
                mma_f16(C[nj],   aQl[ks], bk);
                mma_f16(C[nj+1], aQl[ks], bk + 2);
            }
        }

        // ---- causal mask (last block only) ----
        if (kb == nkb - 1) {
#pragma unroll
            for (int nj = 0; nj < 16; nj++) {
                int col = kb*128 + nj*8 + 2*(lane & 3);
                if (col     > r0    ) C[nj][0] = -1e30f;
                if (col + 1 > r0    ) C[nj][1] = -1e30f;
                if (col     > r0 + 8) C[nj][2] = -1e30f;
                if (col + 1 > r0 + 8) C[nj][3] = -1e30f;
            }
        }

        // ---- online softmax ----
        float mx0 = -1e30f, mx1 = -1e30f;
#pragma unroll
        for (int nj = 0; nj < 16; nj++) {
            mx0 = fmaxf(mx0, fmaxf(C[nj][0], C[nj][1]));
            mx1 = fmaxf(mx1, fmaxf(C[nj][2], C[nj][3]));
        }
        mx0 = fmaxf(mx0, __shfl_xor_sync(0xffffffffu, mx0, 1));
        mx0 = fmaxf(mx0, __shfl_xor_sync(0xffffffffu, mx0, 2));
        mx1 = fmaxf(mx1, __shfl_xor_sync(0xffffffffu, mx1, 1));
        mx1 = fmaxf(mx1, __shfl_xor_sync(0xffffffffu, mx1, 2));
        float mn0 = fmaxf(m0, mx0), mn1 = fmaxf(m1, mx1);
        float a0 = __expf(m0 - mn0), a1 = __expf(m1 - mn1);
        m0 = mn0; m1 = mn1;
        float s0sum = 0.f, s1sum = 0.f;
#pragma unroll
        for (int nj = 0; nj < 16; nj++) {
            C[nj][0] = __expf(C[nj][0] - mn0); s0sum += C[nj][0];
            C[nj][1] = __expf(C[nj][1] - mn0); s0sum += C[nj][1];
            C[nj][2] = __expf(C[nj][2] - mn1); s1sum += C[nj][2];
            C[nj][3] = __expf(C[nj][3] - mn1); s1sum += C[nj][3];
        }
        s0sum += __shfl_xor_sync(0xffffffffu, s0sum, 1);
        s0sum += __shfl_xor_sync(0xffffffffu, s0sum, 2);
        s1sum += __shfl_xor_sync(0xffffffffu, s1sum, 1);
        s1sum += __shfl_xor_sync(0xffffffffu, s1sum, 2);
        l0 = l0 * a0 + s0sum;
        l1 = l1 * a1 + s1sum;
#pragma unroll
        for (int nj = 0; nj < 8; nj++) {
            O[nj][0] *= a0; O[nj][1] *= a0;
            O[nj][2] *= a1; O[nj][3] *= a1;
        }

        // ---- O += P V (fp16), P repacked from C in registers ----
#pragma unroll
        for (int ki = 0; ki < 8; ki++) {
            uint32_t aP[4];
            aP[0] = f16pair(C[2*ki  ][0], C[2*ki  ][1]);
            aP[1] = f16pair(C[2*ki  ][2], C[2*ki  ][3]);
            aP[2] = f16pair(C[2*ki+1][0], C[2*ki+1][1]);
            aP[3] = f16pair(C[2*ki+1][2], C[2*ki+1][3]);
#pragma unroll
            for (int nj = 0; nj < 8; nj += 2) {
                uint32_t bv[4];
                int mm = lane >> 3;
                int row = ki*16 + (mm & 1)*8 + (lane & 7);
                int ch  = nj + (mm >> 1);
                uint32_t off = row*128 + ((ch ^ (row & 7)) << 4);
                ldsm_x4_t(bv, tV + off);
                mma_f16(O[nj],   aP, bv);
                mma_f16(O[nj+1], aP, bv + 2);
            }
        }
        __syncthreads();
    }

    // ---- epilogue: normalize, split fp16 hi/lo, write [B,T,C] ----
    const float i0 = 1.f / l0, i1 = 1.f / l1;
    const int b = bh >> 4, hh = bh & 15;
#pragma unroll
    for (int nj = 0; nj < 8; nj++) {
        int col = hh*HDIM + nj*8 + 2*(lane & 3);
        size_t o0 = ((size_t)b*TQ + r0    ) * CD + col;
        size_t o1 = ((size_t)b*TQ + r0 + 8) * CD + col;
        uint32_t hi, lo;
        f16split2(O[nj][0]*i0, O[nj][1]*i0, hi, lo);
        *(uint32_t*)(Yh + o0) = hi;
        *(uint32_t*)(Yl + o0) = lo;
        f16split2(O[nj][2]*i1, O[nj][3]*i1, hi, lo);
        *(uint32_t*)(Yh + o1) = hi;
        *(uint32_t*)(Yl + o1) = lo;
    }
#undef AT_LOAD
}

// ---------------------------------------------------------------------------
extern "C" void kernel_launch(void* const* d_in, const int* in_sizes, int n_in,
                              void* d_out, int out_size)
{
    const float* x      = (const float*)d_in[0];
    const float* W_attn = (const float*)d_in[1];
    const float* b_attn = (const float*)d_in[2];
    const float* W_proj = (const float*)d_in[3];
    const float* b_proj = (const float*)d_in[4];
    float* out  = (float*)d_out;
    float* Kout = out + (size_t)YSZ;
    float* Vout = out + 2*(size_t)YSZ;

    __half *xh, *xl, *Yh, *Yl, *WaT, *WpT, *Qfh, *Qfl, *Kf, *Vf;
    cudaGetSymbolAddress((void**)&xh,  g_xh);
    cudaGetSymbolAddress((void**)&xl,  g_xl);
    cudaGetSymbolAddress((void**)&Yh,  g_Yh);
    cudaGetSymbolAddress((void**)&Yl,  g_Yl);
    cudaGetSymbolAddress((void**)&WaT, g_WaT);
    cudaGetSymbolAddress((void**)&WpT, g_WpT);
    cudaGetSymbolAddress((void**)&Qfh, g_Qfh);
    cudaGetSymbolAddress((void**)&Qfl, g_Qfl);
    cudaGetSymbolAddress((void**)&Kf,  g_Kf);
    cudaGetSymbolAddress((void**)&Vf,  g_Vf);

    static int attr_done = 0;
    if (!attr_done) {
        cudaFuncSetAttribute(attn3, cudaFuncAttributeMaxDynamicSharedMemorySize, (int)ATTN_SMEM);
        cudaFuncSetAttribute(mma_gemm, cudaFuncAttributeMaxDynamicSharedMemorySize, GEMM_SMEM);
        attr_done = 1;
    }

    // 1) precision prep
    split_kernel<<<(MROWS*CD/4 + 255)/256, 256>>>(x, xh, xl, MROWS*CD/4);
    tsplit_kernel<<<dim3(3*CD/32, CD/32), 256>>>(W_attn, WaT, CD, 3*CD);
    tsplit_kernel<<<dim3(CD/32, CD/32), 256>>>(W_proj, WpT, CD, CD);

    // 2) qkv GEMM (2-term fp16, 2 CTAs/SM) -> Q hi/lo, K/V fp16 + fp32 outputs
    mma_gemm<<<dim3(3*CD/128, MROWS/128), 256, GEMM_SMEM>>>(
        xh, xl, WaT, b_attn, 0, nullptr, Kout, Vout);

    // 3) tensor-core causal flash attention -> Yh/Yl fp16
    attn3<<<dim3(TQ/64, BATCH*NHEAD), 128, ATTN_SMEM>>>(
        Qfh, Qfl, Kf, Vf, Yh, Yl);

    // 4) proj GEMM (2-term fp16) -> y
    mma_gemm<<<dim3(CD/128, MROWS/128), 256, GEMM_SMEM>>>(
        Yh, Yl, WpT, b_proj, 1, out, nullptr, nullptr);
}

// round 10
// speedup vs baseline: 14.8596x; 1.5436x over previous
#include <cuda_runtime.h>
#include <cuda_fp16.h>
#include <cstdint>

// Problem constants
#define TQ    2048
#define CD    1024
#define NHEAD 16
#define HDIM  64
#define BATCH 2
#define MROWS (BATCH*TQ)        // 4096
#define YSZ   (BATCH*TQ*CD)

// ---------------- mma.sync helpers (compute_80 baseline; HMMA on sm_103) ----
__device__ __forceinline__ uint32_t smem_u32(const void* p) {
    uint32_t a;
    asm("{ .reg .u64 t; cvta.to.shared.u64 t, %1; cvt.u32.u64 %0, t; }" : "=r"(a) : "l"(p));
    return a;
}
__device__ __forceinline__ void cp_async16(uint32_t saddr, const void* g) {
    asm volatile("cp.async.cg.shared.global [%0], [%1], 16;" :: "r"(saddr), "l"(g));
}
#define CP_COMMIT() asm volatile("cp.async.commit_group;" ::: "memory")
#define CP_WAIT0()  asm volatile("cp.async.wait_group 0;" ::: "memory")
#define CP_WAIT1()  asm volatile("cp.async.wait_group 1;" ::: "memory")

__device__ __forceinline__ void ldsm_x4(uint32_t* r, uint32_t addr) {
    asm volatile("ldmatrix.sync.aligned.m8n8.x4.shared.b16 {%0,%1,%2,%3}, [%4];"
        : "=r"(r[0]), "=r"(r[1]), "=r"(r[2]), "=r"(r[3]) : "r"(addr));
}
__device__ __forceinline__ void ldsm_x4_t(uint32_t* r, uint32_t addr) {
    asm volatile("ldmatrix.sync.aligned.m8n8.x4.trans.shared.b16 {%0,%1,%2,%3}, [%4];"
        : "=r"(r[0]), "=r"(r[1]), "=r"(r[2]), "=r"(r[3]) : "r"(addr));
}
__device__ __forceinline__ void mma_f16(float* c, const uint32_t* a, const uint32_t* b) {
    asm volatile("mma.sync.aligned.m16n8k16.row.col.f32.f16.f16.f32 "
        "{%0,%1,%2,%3}, {%4,%5,%6,%7}, {%8,%9}, {%0,%1,%2,%3};"
        : "+f"(c[0]), "+f"(c[1]), "+f"(c[2]), "+f"(c[3])
        : "r"(a[0]), "r"(a[1]), "r"(a[2]), "r"(a[3]), "r"(b[0]), "r"(b[1]));
}
// pack (lo, hi) floats -> f16x2 register (lo in low half)
__device__ __forceinline__ uint32_t f16pair(float lo, float hi) {
    uint32_t d;
    asm("cvt.rn.f16x2.f32 %0, %1, %2;" : "=r"(d) : "f"(hi), "f"(lo));
    return d;
}

// ---------------- global scratch (no allocation allowed) ----------------
__device__ __half g_Qf[BATCH*NHEAD*TQ*HDIM];
__device__ __half g_Kf[BATCH*NHEAD*TQ*HDIM];
__device__ __half g_Vf[BATCH*NHEAD*TQ*HDIM];
__device__ __half g_xf[MROWS*CD];
__device__ __half g_Yf[MROWS*CD];
__device__ __half g_WaT[3*CD*CD];     // W_attn^T fp16 [3072,1024]
__device__ __half g_WpT[CD*CD];       // W_proj^T fp16 [1024,1024]

// ---------------- convert / transpose kernels ----------------
__global__ __launch_bounds__(256) void cvt_kernel(
    const float* __restrict__ src, __half* __restrict__ dst, int n4)
{
    int i = blockIdx.x * 256 + threadIdx.x;
    if (i >= n4) return;
    float4 v = ((const float4*)src)[i];
    __half h[4] = {__float2half(v.x), __float2half(v.y),
                   __float2half(v.z), __float2half(v.w)};
    ((uint2*)dst)[i] = *(uint2*)h;
}

// transpose: W [K,N] fp32 -> T fp16 [N,K]
__global__ __launch_bounds__(256) void tcvt_kernel(
    const float* __restrict__ W, __half* __restrict__ Th, int K, int N)
{
    __shared__ float tile[32][33];
    int bx = blockIdx.x * 32, by = blockIdx.y * 32;
    int tx = threadIdx.x & 31, ty = threadIdx.x >> 5;
#pragma unroll
    for (int r = ty; r < 32; r += 8)
        tile[r][tx] = W[(size_t)(by + r) * N + bx + tx];
    __syncthreads();
#pragma unroll
    for (int r = ty; r < 32; r += 8)
        Th[(size_t)(bx + r) * K + by + tx] = __float2half(tile[tx][r]);
}

// ---------------- mma.sync single-term fp16 GEMM ----------------
// C = A @ B^T + bias (fp32 accum);  CTA 128x128, 8 warps (32x64 warp tiles),
// K-chunk 64, 2 stages (64KB), 2 CTAs/SM.
#define TILE_SZ   16384
#define STAGE_SZ  (2*TILE_SZ)      // A | B = 32KB
#define GEMM_SMEM (2*STAGE_SZ)     // 64KB

__global__ __launch_bounds__(256, 2) void mma_gemm(
    const __half* __restrict__ A, const __half* __restrict__ B,
    const float* __restrict__ bias, int mode,
    float* __restrict__ out, float* __restrict__ Kout, float* __restrict__ Vout)
{
    extern __shared__ __align__(1024) char sm[];
    const uint32_t sb = smem_u32(sm);
    const int tid = threadIdx.x, lane = tid & 31, wid = tid >> 5;
    const int wm = wid & 3, wn = wid >> 2;
    const int m0 = blockIdx.y * 128, n0 = blockIdx.x * 128;

    int lr[4], lsw[4];
#pragma unroll
    for (int p = 0; p < 4; p++) {
        int i = tid + p * 256;
        int r = i >> 3, c = i & 7;
        lr[p] = r;
        lsw[p] = r * 128 + ((c ^ (r & 7)) << 4);
    }

#define LOAD_CHUNK(kc, stage) do {                                          \
        uint32_t s0 = sb + (stage) * STAGE_SZ;                              \
        int kcol = (kc) * 64;                                               \
        _Pragma("unroll")                                                   \
        for (int p = 0; p < 4; p++) {                                       \
            int c8 = ((tid + p*256) & 7) * 8;                               \
            size_t ga = (size_t)(m0 + lr[p]) * CD + kcol + c8;              \
            size_t gb = (size_t)(n0 + lr[p]) * CD + kcol + c8;              \
            cp_async16(s0 +           lsw[p], A + ga);                      \
            cp_async16(s0 + TILE_SZ + lsw[p], B + gb);                      \
        }                                                                   \
    } while (0)

    float C[2][8][4];
#pragma unroll
    for (int mi = 0; mi < 2; mi++)
#pragma unroll
        for (int ni = 0; ni < 8; ni++)
#pragma unroll
            for (int q = 0; q < 4; q++) C[mi][ni][q] = 0.f;

    const int ar  = wm*32 + (lane & 15);
    const int ach = (lane >> 4);
    const int brr = wn*64 + ((lane >> 4) & 1)*8 + (lane & 7);
    const int bcc = (lane >> 3) & 1;

    LOAD_CHUNK(0, 0); CP_COMMIT();
    LOAD_CHUNK(1, 1); CP_COMMIT();

    for (int kc = 0; kc < 16; kc++) {
        if (kc == 15) { CP_WAIT0(); } else { CP_WAIT1(); }
        __syncthreads();

        const uint32_t s0 = sb + (kc & 1) * STAGE_SZ;
        const uint32_t tA = s0, tB = s0 + TILE_SZ;

#pragma unroll
        for (int ks = 0; ks < 4; ks++) {
            uint32_t aF[2][4];
#pragma unroll
            for (int mi = 0; mi < 2; mi++) {
                int r = ar + mi*16;
                int c = ks*2 + ach;
                uint32_t off = r*128 + ((c ^ (r & 7)) << 4);
                ldsm_x4(aF[mi], tA + off);
            }
#pragma unroll
            for (int ni = 0; ni < 8; ni += 2) {
                uint32_t bv[4];
                int row = brr + ni*8;
                int c = ks*2 + bcc;
                uint32_t off = row*128 + ((c ^ (row & 7)) << 4);
                ldsm_x4(bv, tB + off);
                mma_f16(C[0][ni],   aF[0], bv);
                mma_f16(C[1][ni],   aF[1], bv);
                mma_f16(C[0][ni+1], aF[0], bv + 2);
                mma_f16(C[1][ni+1], aF[1], bv + 2);
            }
        }
        __syncthreads();
        if (kc + 2 < 16) { LOAD_CHUNK(kc + 2, kc & 1); CP_COMMIT(); }
    }

    // Epilogue
    const int mbase = m0 + wm*32 + (lane >> 2);
    const int npair = 2*(lane & 3);
#pragma unroll
    for (int mi = 0; mi < 2; mi++) {
#pragma unroll
        for (int half = 0; half < 2; half++) {
            int m = mbase + mi*16 + half*8;
            int b = m >> 11, tt = m & (TQ - 1);
#pragma unroll
            for (int ni = 0; ni < 8; ni++) {
                int n = n0 + wn*64 + ni*8 + npair;
                float2 bvs = *(const float2*)(bias + n);
                float2 v;
                v.x = C[mi][ni][half*2+0] + bvs.x;
                v.y = C[mi][ni][half*2+1] + bvs.y;
                if (mode == 0) {
                    int sec = n >> 10, within = n & 1023;
                    int h = within >> 6, dd = within & 63;
                    size_t idx = ((size_t)(b*NHEAD + h)*TQ + tt)*HDIM + dd;
                    if (sec == 0) {
                        __half2 hv = __floats2half2_rn(v.x * 0.125f, v.y * 0.125f);
                        *(__half2*)(g_Qf + idx) = hv;
                    } else if (sec == 1) {
                        *(float2*)(Kout + idx) = v;
                        *(__half2*)(g_Kf + idx) = __floats2half2_rn(v.x, v.y);
                    } else {
                        *(float2*)(Vout + idx) = v;
                        *(__half2*)(g_Vf + idx) = __floats2half2_rn(v.x, v.y);
                    }
                } else {
                    *(float2*)(out + (size_t)m*CD + n) = v;
                }
            }
        }
    }
#undef LOAD_CHUNK
}

// ---------------------------------------------------------------------------
// Tensor-core flash attention: CTA = 64 q-rows (4 warps), key blocks of 128.
// S = Q K^T single fp16; PV single fp16; fp32 accum + online softmax.
// ---------------------------------------------------------------------------
#define AT_STAGE 32768                 // Kf(16K) | V(16K)
#define ATTN_SMEM (2*AT_STAGE)         // 64KB

__global__ __launch_bounds__(128) void attn3(
    const __half* __restrict__ Qf, const __half* __restrict__ Kf,
    const __half* __restrict__ Vf, __half* __restrict__ Yf)
{
    extern __shared__ __align__(1024) char sm[];
    const uint32_t sb = smem_u32(sm);
    const int tid = threadIdx.x, lane = tid & 31, w = tid >> 5;
    const int bh = blockIdx.y;
    const int qt = gridDim.x - 1 - blockIdx.x;   // big tiles first
    const int q0 = qt * 64;
    const int nkb = (q0 + 191) >> 7;
    const size_t qbase = (size_t)bh * TQ;

    // Resident Q A-fragments
    const int r0 = q0 + w*16 + (lane >> 2);
    uint32_t aQ[4][4];
#pragma unroll
    for (int ks = 0; ks < 4; ks++) {
        int k = ks*16 + 2*(lane & 3);
        aQ[ks][0] = *(const uint32_t*)(Qf + (qbase + r0    )*HDIM + k);
        aQ[ks][1] = *(const uint32_t*)(Qf + (qbase + r0 + 8)*HDIM + k);
        aQ[ks][2] = *(const uint32_t*)(Qf + (qbase + r0    )*HDIM + k + 8);
        aQ[ks][3] = *(const uint32_t*)(Qf + (qbase + r0 + 8)*HDIM + k + 8);
    }

#define AT_LOAD(kb, s) do {                                                  \
        uint32_t s0 = sb + (s) * AT_STAGE;                                   \
        int k0 = (kb) * 128;                                                 \
        _Pragma("unroll")                                                    \
        for (int p = 0; p < 8; p++) {                                        \
            int i = tid + p * 128;                                           \
            int r = i >> 3, c = i & 7;                                       \
            uint32_t sw = r*128 + ((c ^ (r & 7)) << 4);                      \
            size_t g = (qbase + k0 + r) * HDIM + c*8;                        \
            cp_async16(s0 +         sw, Kf + g);                             \
            cp_async16(s0 + 16384 + sw, Vf + g);                             \
        }                                                                    \
    } while (0)

    float m0 = -1e30f, m1 = -1e30f, l0 = 0.f, l1 = 0.f;
    float O[8][4];
#pragma unroll
    for (int nj = 0; nj < 8; nj++)
#pragma unroll
        for (int q = 0; q < 4; q++) O[nj][q] = 0.f;

    AT_LOAD(0, 0); CP_COMMIT();

    for (int kb = 0; kb < nkb; kb++) {
        const bool more = (kb + 1 < nkb);
        if (more) { AT_LOAD(kb + 1, (kb + 1) & 1); CP_COMMIT(); }
        if (more) { CP_WAIT1(); } else { CP_WAIT0(); }
        __syncthreads();
        const uint32_t s0 = sb + (kb & 1) * AT_STAGE;
        const uint32_t tKF = s0, tV = s0 + 16384;

        // ---- S = Q K^T (single fp16), 16 n-tiles of 8 keys ----
        float C[16][4];
#pragma unroll
        for (int nj = 0; nj < 16; nj++)
#pragma unroll
            for (int q = 0; q < 4; q++) C[nj][q] = 0.f;

#pragma unroll
        for (int ks = 0; ks < 4; ks++) {
#pragma unroll
            for (int nj = 0; nj < 16; nj += 2) {
                uint32_t bk[4];
                int mm = lane >> 3;
                int row = nj*8 + (mm >> 1)*8 + (lane & 7);
                int ch  = 2*ks + (mm & 1);
                uint32_t off = row*128 + ((ch ^ (row & 7)) << 4);
                ldsm_x4(bk, tKF + off);
                mma_f16(C[nj],   aQ[ks], bk);
                mma_f16(C[nj+1], aQ[ks], bk + 2);
            }
        }

        // ---- causal mask (last block only) ----
        if (kb == nkb - 1) {
#pragma unroll
            for (int nj = 0; nj < 16; nj++) {
                int col = kb*128 + nj*8 + 2*(lane & 3);
                if (col     > r0    ) C[nj][0] = -1e30f;
                if (col + 1 > r0    ) C[nj][1] = -1e30f;
                if (col     > r0 + 8) C[nj][2] = -1e30f;
                if (col + 1 > r0 + 8) C[nj][3] = -1e30f;
            }
        }

        // ---- online softmax ----
        float mx0 = -1e30f, mx1 = -1e30f;
#pragma unroll
        for (int nj = 0; nj < 16; nj++) {
            mx0 = fmaxf(mx0, fmaxf(C[nj][0], C[nj][1]));
            mx1 = fmaxf(mx1, fmaxf(C[nj][2], C[nj][3]));
        }
        mx0 = fmaxf(mx0, __shfl_xor_sync(0xffffffffu, mx0, 1));
        mx0 = fmaxf(mx0, __shfl_xor_sync(0xffffffffu, mx0, 2));
        mx1 = fmaxf(mx1, __shfl_xor_sync(0xffffffffu, mx1, 1));
        mx1 = fmaxf(mx1, __shfl_xor_sync(0xffffffffu, mx1, 2));
        float mn0 = fmaxf(m0, mx0), mn1 = fmaxf(m1, mx1);
        float a0 = __expf(m0 - mn0), a1 = __expf(m1 - mn1);
        m0 = mn0; m1 = mn1;
        float s0sum = 0.f, s1sum = 0.f;
#pragma unroll
        for (int nj = 0; nj < 16; nj++) {
            C[nj][0] = __expf(C[nj][0] - mn0); s0sum += C[nj][0];
            C[nj][1] = __expf(C[nj][1] - mn0); s0sum += C[nj][1];
            C[nj][2] = __expf(C[nj][2] - mn1); s1sum += C[nj][2];
            C[nj][3] = __expf(C[nj][3] - mn1); s1sum += C[nj][3];
        }
        s0sum += __shfl_xor_sync(0xffffffffu, s0sum, 1);
        s0sum += __shfl_xor_sync(0xffffffffu, s0sum, 2);
        s1sum += __shfl_xor_sync(0xffffffffu, s1sum, 1);
        s1sum += __shfl_xor_sync(0xffffffffu, s1sum, 2);
        l0 = l0 * a0 + s0sum;
        l1 = l1 * a1 + s1sum;
#pragma unroll
        for (int nj = 0; nj < 8; nj++) {
            O[nj][0] *= a0; O[nj][1] *= a0;
            O[nj][2] *= a1; O[nj][3] *= a1;
        }

        // ---- O += P V (fp16), P repacked from C in registers ----
#pragma unroll
        for (int ki = 0; ki < 8; ki++) {
            uint32_t aP[4];
            aP[0] = f16pair(C[2*ki  ][0], C[2*ki  ][1]);
            aP[1] = f16pair(C[2*ki  ][2], C[2*ki  ][3]);
            aP[2] = f16pair(C[2*ki+1][0], C[2*ki+1][1]);
            aP[3] = f16pair(C[2*ki+1][2], C[2*ki+1][3]);
#pragma unroll
            for (int nj = 0; nj < 8; nj += 2) {
                uint32_t bv[4];
                int mm = lane >> 3;
                int row = ki*16 + (mm & 1)*8 + (lane & 7);
                int ch  = nj + (mm >> 1);
                uint32_t off = row*128 + ((ch ^ (row & 7)) << 4);
                ldsm_x4_t(bv, tV + off);
                mma_f16(O[nj],   aP, bv);
                mma_f16(O[nj+1], aP, bv + 2);
            }
        }
        __syncthreads();
    }

    // ---- epilogue: normalize, write fp16 Y in [B,T,C] ----
    const float i0 = 1.f / l0, i1 = 1.f / l1;
    const int b = bh >> 4, hh = bh & 15;
#pragma unroll
    for (int nj = 0; nj < 8; nj++) {
        int col = hh*HDIM + nj*8 + 2*(lane & 3);
        size_t o0 = ((size_t)b*TQ + r0    ) * CD + col;
        size_t o1 = ((size_t)b*TQ + r0 + 8) * CD + col;
        *(__half2*)(Yf + o0) = __floats2half2_rn(O[nj][0]*i0, O[nj][1]*i0);
        *(__half2*)(Yf + o1) = __floats2half2_rn(O[nj][2]*i1, O[nj][3]*i1);
    }
#undef AT_LOAD
}

// ---------------------------------------------------------------------------
extern "C" void kernel_launch(void* const* d_in, const int* in_sizes, int n_in,
                              void* d_out, int out_size)
{
    const float* x      = (const float*)d_in[0];
    const float* W_attn = (const float*)d_in[1];
    const float* b_attn = (const float*)d_in[2];
    const float* W_proj = (const float*)d_in[3];
    const float* b_proj = (const float*)d_in[4];
    float* out  = (float*)d_out;
    float* Kout = out + (size_t)YSZ;
    float* Vout = out + 2*(size_t)YSZ;

    __half *xf, *Yf, *WaT, *WpT, *Qf, *Kf, *Vf;
    cudaGetSymbolAddress((void**)&xf,  g_xf);
    cudaGetSymbolAddress((void**)&Yf,  g_Yf);
    cudaGetSymbolAddress((void**)&WaT, g_WaT);
    cudaGetSymbolAddress((void**)&WpT, g_WpT);
    cudaGetSymbolAddress((void**)&Qf,  g_Qf);
    cudaGetSymbolAddress((void**)&Kf,  g_Kf);
    cudaGetSymbolAddress((void**)&Vf,  g_Vf);

    static int attr_done = 0;
    if (!attr_done) {
        cudaFuncSetAttribute(attn3, cudaFuncAttributeMaxDynamicSharedMemorySize, (int)ATTN_SMEM);
        cudaFuncSetAttribute(mma_gemm, cudaFuncAttributeMaxDynamicSharedMemorySize, GEMM_SMEM);
        attr_done = 1;
    }

    // 1) precision prep: fp32 -> fp16
    cvt_kernel<<<(MROWS*CD/4 + 255)/256, 256>>>(x, xf, MROWS*CD/4);
    tcvt_kernel<<<dim3(3*CD/32, CD/32), 256>>>(W_attn, WaT, CD, 3*CD);
    tcvt_kernel<<<dim3(CD/32, CD/32), 256>>>(W_proj, WpT, CD, CD);

    // 2) qkv GEMM (fp16, fp32 accum) -> Q/K/V fp16 + K/V fp32 outputs
    mma_gemm<<<dim3(3*CD/128, MROWS/128), 256, GEMM_SMEM>>>(
        xf, WaT, b_attn, 0, nullptr, Kout, Vout);

    // 3) tensor-core causal flash attention -> Yf fp16
    attn3<<<dim3(TQ/64, BATCH*NHEAD), 128, ATTN_SMEM>>>(Qf, Kf, Vf, Yf);

    // 4) proj GEMM -> y
    mma_gemm<<<dim3(CD/128, MROWS/128), 256, GEMM_SMEM>>>(
        Yf, WpT, b_proj, 1, out, nullptr, nullptr);
}